// round 2
// baseline (speedup 1.0000x reference)
#include <cuda_runtime.h>
#include <cstdint>

// ---------------- problem constants ----------------
#define BB      2
#define DD      2048
#define LL      4096
#define N3      6144          // 3*D
#define NFFT    8192          // 2*L
#define HALF_N  4096
#define ORD     64            // filter order

// ---------------- scratch (device globals; no allocation allowed) ----------------
__device__ float  g_u [(size_t)BB * N3 * LL];     // in_proj output, (b, c, l)
__device__ float  g_v [(size_t)BB * DD * LL];     // v * x1, (b, d, l)
__device__ float  g_x0[(size_t)BB * DD * LL];     // x0 gate, (b, d, l)
__device__ float  g_g [(size_t)BB * DD * LL];     // gated conv output, (b, d, l)
__device__ float  g_k [(size_t)DD * LL];          // filter k, (d, l)
__device__ float  g_h [(size_t)LL * ORD];         // MLP features h, (l, o)
__device__ float2 g_kf[(size_t)DD * NFFT];        // K spectra (full complex)
__device__ float2 g_tw[HALF_N];                   // twiddles exp(-2*pi*i*j/NFFT)

// ---------------- twiddle table ----------------
__global__ void k_twiddle() {
    int j = blockIdx.x * blockDim.x + threadIdx.x;
    if (j < HALF_N) {
        double a = -2.0 * 3.14159265358979323846 * (double)j / (double)NFFT;
        g_tw[j] = make_float2((float)cos(a), (float)sin(a));
    }
}

// ---------------- in_proj GEMM: C[m,n] = x[m,:] . W[n,:] + b[n], store (b,n,l) ----------------
__global__ __launch_bounds__(256)
void k_gemm_in(const float* __restrict__ A, const float* __restrict__ Bw,
               const float* __restrict__ bias)
{
    __shared__ float As[8][128];
    __shared__ float Bs[8][128];
    const int tid = threadIdx.x;
    const int m0 = blockIdx.y * 128;
    const int n0 = blockIdx.x * 128;
    const int lr = tid >> 1;
    const int lc = (tid & 1) << 2;
    const float* Ap = A  + (size_t)(m0 + lr) * 2048 + lc;
    const float* Bp = Bw + (size_t)(n0 + lr) * 2048 + lc;
    const int tr = (tid >> 4) << 3;     // m offset
    const int tc = (tid & 15) << 3;     // n offset
    float c[8][8];
#pragma unroll
    for (int i = 0; i < 8; i++)
#pragma unroll
        for (int j = 0; j < 8; j++) c[i][j] = 0.f;

    for (int k0 = 0; k0 < 2048; k0 += 8) {
        float4 a4 = *(const float4*)Ap;
        float4 b4 = *(const float4*)Bp;
        Ap += 8; Bp += 8;
        As[lc + 0][lr] = a4.x; As[lc + 1][lr] = a4.y;
        As[lc + 2][lr] = a4.z; As[lc + 3][lr] = a4.w;
        Bs[lc + 0][lr] = b4.x; Bs[lc + 1][lr] = b4.y;
        Bs[lc + 2][lr] = b4.z; Bs[lc + 3][lr] = b4.w;
        __syncthreads();
#pragma unroll
        for (int kk = 0; kk < 8; kk++) {
            float ar[8], br[8];
#pragma unroll
            for (int i = 0; i < 8; i++) ar[i] = As[kk][tr + i];
#pragma unroll
            for (int j = 0; j < 8; j++) br[j] = Bs[kk][tc + j];
#pragma unroll
            for (int i = 0; i < 8; i++)
#pragma unroll
                for (int j = 0; j < 8; j++) c[i][j] += ar[i] * br[j];
        }
        __syncthreads();
    }
    // store transposed: g_u[(b*N3 + n)*LL + l]
    const int b = m0 >> 12;
    const int lbase = (m0 & (LL - 1)) + tr;
#pragma unroll
    for (int j = 0; j < 8; j++) {
        int n = n0 + tc + j;
        float bi = bias[n];
        float* up = g_u + ((size_t)b * N3 + n) * LL + lbase;
        float4 v0 = make_float4(c[0][j] + bi, c[1][j] + bi, c[2][j] + bi, c[3][j] + bi);
        float4 v1 = make_float4(c[4][j] + bi, c[5][j] + bi, c[6][j] + bi, c[7][j] + bi);
        *(float4*)(up)     = v0;
        *(float4*)(up + 4) = v1;
    }
}

// ---------------- depthwise short conv (K=3, causal) + split + gate v*x1 ----------------
__global__ void k_shortconv(const float* __restrict__ sw, const float* __restrict__ sb)
{
    int l = blockIdx.x * blockDim.x + threadIdx.x;
    int d = blockIdx.y;
    int b = blockIdx.z;
    if (l >= LL) return;

    float r[3];
#pragma unroll
    for (int part = 0; part < 3; part++) {
        int cc = part * DD + d;
        const float* u = g_u + ((size_t)b * N3 + cc) * LL;
        float w0 = sw[cc * 3 + 0], w1 = sw[cc * 3 + 1], w2 = sw[cc * 3 + 2];
        float acc = sb[cc] + w2 * u[l];
        if (l >= 1) acc += w1 * u[l - 1];
        if (l >= 2) acc += w0 * u[l - 2];
        r[part] = acc;
    }
    size_t o = ((size_t)b * DD + d) * LL + l;
    g_x0[o] = r[0];
    g_v[o]  = r[2] * r[1];
}

// ---------------- filter MLP features h(l) ----------------
__global__ __launch_bounds__(256)
void k_filter_h(const float* __restrict__ w0, const float* __restrict__ b0,
                const float* __restrict__ fr,
                const float* __restrict__ w1, const float* __restrict__ b1,
                const float* __restrict__ w2, const float* __restrict__ b2)
{
    __shared__ float hb[2][4][ORD];
    int o  = threadIdx.x & 63;
    int sl = threadIdx.x >> 6;      // 0..3
    int l  = blockIdx.x * 4 + sl;

    float t    = (float)l * (1.0f / (LL - 1));
    float wang = 6.28318530717958647692f * (float)l * (1.0f / LL);
    float ang  = 1e-4f * wang;
    float z0 = t, z1 = cosf(ang), z2 = -sinf(ang);
    float f = fr[o];

    float h = sinf(f * (w0[o * 3 + 0] * z0 + w0[o * 3 + 1] * z1 + w0[o * 3 + 2] * z2 + b0[o]));
    hb[0][sl][o] = h;
    __syncthreads();

    float acc = b1[o];
#pragma unroll
    for (int j = 0; j < ORD; j++) acc += w1[o * ORD + j] * hb[0][sl][j];
    h = sinf(f * acc);
    hb[1][sl][o] = h;
    __syncthreads();

    acc = b2[o];
#pragma unroll
    for (int j = 0; j < ORD; j++) acc += w2[o * ORD + j] * hb[1][sl][j];
    h = sinf(f * acc);
    g_h[(size_t)l * ORD + o] = h;
}

// ---------------- filter k(d,l) = (h(l) . w3[d]) * exp(-t*|delta_d|) ----------------
#define MIN_DECAY (-3.0701134573253937f)
#define MAX_DECAY (-15.350567286626969f)
__global__ __launch_bounds__(256)
void k_filter_k(const float* __restrict__ W3)
{
    __shared__ float hs[64][65];
    __shared__ float ws[64][64];
    int l0 = blockIdx.x * 64;
    int d0 = blockIdx.y * 64;
    for (int i = threadIdx.x; i < 64 * 64; i += 256) {
        int r = i >> 6, cidx = i & 63;
        hs[r][cidx] = g_h[(size_t)(l0 + r) * ORD + cidx];
        ws[r][cidx] = W3[(size_t)(d0 + r) * ORD + cidx];
    }
    __syncthreads();
    for (int i = threadIdx.x; i < 64 * 64; i += 256) {
        int ll = i & 63;        // varies within warp -> coalesced store
        int dd = i >> 6;
        float acc = 0.f;
#pragma unroll
        for (int j = 0; j < ORD; j++) acc += ws[dd][j] * hs[ll][j];
        int d = d0 + dd, l = l0 + ll;
        float delta = MIN_DECAY + (MAX_DECAY - MIN_DECAY) * (float)d * (1.0f / (DD - 1));
        float decay = expf(-((float)l * (1.0f / (LL - 1))) * fabsf(delta));
        g_k[(size_t)d * LL + l] = acc * decay;
    }
}

// ---------------- shared-memory radix-2 FFT (N=8192) ----------------
__device__ __forceinline__ void fft8192_shared(float2* sm, const float2* stw, bool inverse)
{
    const int tid = threadIdx.x;
    const int nt  = blockDim.x;
    // bit reverse (13 bits)
    for (int j = tid; j < NFFT; j += nt) {
        int r = __brev(j) >> 19;
        if (r > j) { float2 tmp = sm[j]; sm[j] = sm[r]; sm[r] = tmp; }
    }
    __syncthreads();
#pragma unroll 1
    for (int s = 1; s <= 13; s++) {
        const int half   = 1 << (s - 1);
        const int tshift = 13 - s;
        for (int t = tid; t < HALF_N; t += nt) {
            int j = t & (half - 1);
            int base = ((t >> (s - 1)) << s) + j;
            float2 w = stw[j << tshift];
            float wy = inverse ? -w.y : w.y;
            float2 u = sm[base];
            float2 v = sm[base + half];
            float wvx = w.x * v.x - wy * v.y;
            float wvy = w.x * v.y + wy * v.x;
            sm[base]        = make_float2(u.x + wvx, u.y + wvy);
            sm[base + half] = make_float2(u.x - wvx, u.y - wvy);
        }
        __syncthreads();
    }
}

extern __shared__ float2 dynsm[];

// ---------------- FFT of filter rows ----------------
__global__ void k_fft_k()
{
    float2* sm  = dynsm;            // 8192
    float2* stw = dynsm + NFFT;     // 4096
    const int d = blockIdx.x;
    const int tid = threadIdx.x;
    for (int j = tid; j < HALF_N; j += blockDim.x) stw[j] = g_tw[j];
    const float* kr = g_k + (size_t)d * LL;
    for (int j = tid; j < NFFT; j += blockDim.x)
        sm[j] = make_float2(j < LL ? kr[j] : 0.f, 0.f);
    __syncthreads();
    fft8192_shared(sm, stw, false);
    float2* kf = g_kf + (size_t)d * NFFT;
    for (int j = tid; j < NFFT; j += blockDim.x) kf[j] = sm[j];
}

// ---------------- main FFT conv + bias skip + x0 gate ----------------
__global__ void k_fftconv(const float* __restrict__ fbias)
{
    float2* sm  = dynsm;
    float2* stw = dynsm + NFFT;
    const int ch  = blockIdx.x;       // b*DD + d
    const int d   = ch & (DD - 1);
    const int tid = threadIdx.x;
    const float* v = g_v + (size_t)ch * LL;

    for (int j = tid; j < HALF_N; j += blockDim.x) stw[j] = g_tw[j];
    for (int j = tid; j < NFFT; j += blockDim.x)
        sm[j] = make_float2(j < LL ? v[j] : 0.f, 0.f);
    __syncthreads();
    fft8192_shared(sm, stw, false);

    const float2* kf = g_kf + (size_t)d * NFFT;
    for (int j = tid; j < NFFT; j += blockDim.x) {
        float2 a = sm[j];
        float2 b = kf[j];
        sm[j] = make_float2(a.x * b.x - a.y * b.y, a.x * b.y + a.y * b.x);
    }
    __syncthreads();
    fft8192_shared(sm, stw, true);

    const float bi = fbias[d];
    const float* x0 = g_x0 + (size_t)ch * LL;
    float* g = g_g + (size_t)ch * LL;
    const float inv = 1.0f / (float)NFFT;
    for (int j = tid; j < LL; j += blockDim.x) {
        float y = sm[j].x * inv;
        g[j] = (y + v[j] * bi) * x0[j];
    }
}

// ---------------- out_proj GEMM: out[m,n] = G[:,m] . Wo[n,:] + bo[n] ----------------
__global__ __launch_bounds__(256)
void k_gemm_out(const float* __restrict__ Bw, const float* __restrict__ bias,
                float* __restrict__ Out)
{
    __shared__ float As[8][128];
    __shared__ float Bs[8][128];
    const int tid = threadIdx.x;
    const int m0 = blockIdx.y * 128;
    const int n0 = blockIdx.x * 128;
    const int b  = m0 >> 12;
    const int l0 = m0 & (LL - 1);
    const int ak = tid >> 5;            // 0..7   (k row)
    const int am = (tid & 31) << 2;     // 0..124 (m col)
    const int lr = tid >> 1;
    const int lc = (tid & 1) << 2;
    const float* Ap = g_g + ((size_t)b * DD + ak) * LL + l0 + am;
    const float* Bp = Bw + (size_t)(n0 + lr) * 2048 + lc;
    const int tr = (tid >> 4) << 3;
    const int tc = (tid & 15) << 3;
    float c[8][8];
#pragma unroll
    for (int i = 0; i < 8; i++)
#pragma unroll
        for (int j = 0; j < 8; j++) c[i][j] = 0.f;

    for (int k0 = 0; k0 < 2048; k0 += 8) {
        float4 a4 = *(const float4*)Ap;
        float4 b4 = *(const float4*)Bp;
        Ap += (size_t)8 * LL; Bp += 8;
        *(float4*)&As[ak][am] = a4;
        Bs[lc + 0][lr] = b4.x; Bs[lc + 1][lr] = b4.y;
        Bs[lc + 2][lr] = b4.z; Bs[lc + 3][lr] = b4.w;
        __syncthreads();
#pragma unroll
        for (int kk = 0; kk < 8; kk++) {
            float ar[8], br[8];
#pragma unroll
            for (int i = 0; i < 8; i++) ar[i] = As[kk][tr + i];
#pragma unroll
            for (int j = 0; j < 8; j++) br[j] = Bs[kk][tc + j];
#pragma unroll
            for (int i = 0; i < 8; i++)
#pragma unroll
                for (int j = 0; j < 8; j++) c[i][j] += ar[i] * br[j];
        }
        __syncthreads();
    }
#pragma unroll
    for (int i = 0; i < 8; i++) {
        int m = m0 + tr + i;
        float* op = Out + (size_t)m * 2048 + n0 + tc;
        float4 v0 = make_float4(c[i][0] + bias[n0 + tc + 0], c[i][1] + bias[n0 + tc + 1],
                                c[i][2] + bias[n0 + tc + 2], c[i][3] + bias[n0 + tc + 3]);
        float4 v1 = make_float4(c[i][4] + bias[n0 + tc + 4], c[i][5] + bias[n0 + tc + 5],
                                c[i][6] + bias[n0 + tc + 6], c[i][7] + bias[n0 + tc + 7]);
        *(float4*)(op)     = v0;
        *(float4*)(op + 4) = v1;
    }
}

// ---------------- launch ----------------
extern "C" void kernel_launch(void* const* d_in, const int* in_sizes, int n_in,
                              void* d_out, int out_size)
{
    const float* x    = (const float*)d_in[0];
    const float* iw   = (const float*)d_in[1];
    const float* ib   = (const float*)d_in[2];
    const float* sw   = (const float*)d_in[3];
    const float* sb   = (const float*)d_in[4];
    const float* w0   = (const float*)d_in[5];
    const float* b0   = (const float*)d_in[6];
    const float* fr   = (const float*)d_in[7];
    const float* w1   = (const float*)d_in[8];
    const float* b1   = (const float*)d_in[9];
    const float* w2   = (const float*)d_in[10];
    const float* b2   = (const float*)d_in[11];
    const float* w3   = (const float*)d_in[12];
    const float* fb   = (const float*)d_in[13];
    const float* ow   = (const float*)d_in[14];
    const float* ob   = (const float*)d_in[15];
    float* out = (float*)d_out;

    const int fft_smem = (NFFT + HALF_N) * sizeof(float2);   // 96 KB
    (void)cudaFuncSetAttribute(k_fft_k,   cudaFuncAttributeMaxDynamicSharedMemorySize, fft_smem);
    (void)cudaFuncSetAttribute(k_fftconv, cudaFuncAttributeMaxDynamicSharedMemorySize, fft_smem);

    // filter path (independent of data path)
    k_twiddle<<<8, 512>>>();
    k_filter_h<<<LL / 4, 256>>>(w0, b0, fr, w1, b1, w2, b2);
    k_filter_k<<<dim3(LL / 64, DD / 64), 256>>>(w3);
    k_fft_k<<<DD, 512, fft_smem>>>();

    // data path
    k_gemm_in<<<dim3(N3 / 128, (BB * LL) / 128), 256>>>(x, iw, ib);
    k_shortconv<<<dim3(LL / 256, DD, BB), 256>>>(sw, sb);
    k_fftconv<<<BB * DD, 512, fft_smem>>>(fb);
    k_gemm_out<<<dim3(2048 / 128, (BB * LL) / 128), 256>>>(ow, ob, out);
}

// round 4
// speedup vs baseline: 3.8799x; 3.8799x over previous
#include <cuda_runtime.h>
#include <cuda_bf16.h>
#include <cstdint>

// ---------------- problem constants ----------------
#define BB      2
#define DD      2048
#define LL      4096
#define N3      6144          // 3*D
#define NFFT    8192          // 2*L
#define HALF_N  4096
#define ORD     64            // filter order
#define KDIM    2048          // GEMM K (both GEMMs)
#define MROWS   8192          // GEMM M (B*L)
#define KFW     4097          // stored half-spectrum width

// GEMM tiling
#define Bb_M 128
#define Bb_N 128
#define Bb_K 32
#define NCHUNK (KDIM / Bb_K)          // 64
#define MAT_BYTES  (128 * 32 * 2)     // 8192 per matrix per stage
#define STAGE_BYTES (4 * MAT_BYTES)   // 32768 (Ah, Al, Bh, Bl)
#define GEMM_SMEM  (3 * STAGE_BYTES)  // 98304

// ---------------- scratch (device globals; no allocation allowed) ----------------
__device__ float  g_u [(size_t)BB * N3 * LL];     // in_proj output, (b, c, l)
__device__ float  g_v [(size_t)BB * DD * LL];     // v * x1, (b, d, l)
__device__ float  g_x0[(size_t)BB * DD * LL];     // x0 gate, (b, d, l)
__device__ float  g_g [(size_t)BB * DD * LL];     // gated conv output, (b, d, l)
__device__ float  g_k [(size_t)DD * LL];          // filter k, (d, l)
__device__ float  g_h [(size_t)LL * ORD];         // MLP features h, (l, o)
__device__ float2 g_kf[(size_t)DD * KFW];         // K half-spectra
__device__ float2 g_tw[HALF_N];                   // twiddles

// bf16 split operands
__device__ __nv_bfloat16 g_xh [(size_t)MROWS * KDIM];
__device__ __nv_bfloat16 g_xl [(size_t)MROWS * KDIM];
__device__ __nv_bfloat16 g_wih[(size_t)N3 * KDIM];
__device__ __nv_bfloat16 g_wil[(size_t)N3 * KDIM];
__device__ __nv_bfloat16 g_gh [(size_t)MROWS * KDIM];   // transposed gated output (b,l,d)
__device__ __nv_bfloat16 g_gl [(size_t)MROWS * KDIM];
__device__ __nv_bfloat16 g_woh[(size_t)DD * KDIM];
__device__ __nv_bfloat16 g_wol[(size_t)DD * KDIM];

// ---------------- PTX helpers ----------------
__device__ __forceinline__ uint32_t smem_u32(const void* p) {
    uint32_t a;
    asm("{ .reg .u64 t; cvta.to.shared.u64 t, %1; cvt.u32.u64 %0, t; }" : "=r"(a) : "l"(p));
    return a;
}
__device__ __forceinline__ void cpa16(uint32_t dst, const void* src) {
    asm volatile("cp.async.cg.shared.global [%0], [%1], 16;" :: "r"(dst), "l"(src) : "memory");
}
#define CPA_COMMIT() asm volatile("cp.async.commit_group;" ::: "memory")
#define CPA_WAIT2()  asm volatile("cp.async.wait_group 2;" ::: "memory")
#define CPA_WAIT1()  asm volatile("cp.async.wait_group 1;" ::: "memory")
#define CPA_WAIT0()  asm volatile("cp.async.wait_group 0;" ::: "memory")

#define LDX4(r, addr) \
    asm volatile("ldmatrix.sync.aligned.m8n8.x4.shared.b16 {%0,%1,%2,%3}, [%4];" \
        : "=r"((r)[0]), "=r"((r)[1]), "=r"((r)[2]), "=r"((r)[3]) : "r"(addr))

#define MMA16816(d, a, b0, b1) \
    asm volatile("mma.sync.aligned.m16n8k16.row.col.f32.bf16.bf16.f32 " \
        "{%0,%1,%2,%3}, {%4,%5,%6,%7}, {%8,%9}, {%0,%1,%2,%3};" \
        : "+f"((d)[0]), "+f"((d)[1]), "+f"((d)[2]), "+f"((d)[3]) \
        : "r"((a)[0]), "r"((a)[1]), "r"((a)[2]), "r"((a)[3]), "r"(b0), "r"(b1))

__device__ __forceinline__ uint32_t swz(uint32_t off) {
    return off ^ ((off >> 3) & 0x30u);
}

// ---------------- twiddle table ----------------
__global__ void k_twiddle() {
    int j = blockIdx.x * blockDim.x + threadIdx.x;
    if (j < HALF_N) {
        double a = -2.0 * 3.14159265358979323846 * (double)j / (double)NFFT;
        g_tw[j] = make_float2((float)cos(a), (float)sin(a));
    }
}

// ---------------- fp32 -> bf16 hi/lo split ----------------
__global__ void k_split(const float* __restrict__ in, __nv_bfloat16* __restrict__ hi,
                        __nv_bfloat16* __restrict__ lo, int n4)
{
    int i = blockIdx.x * blockDim.x + threadIdx.x;
    if (i >= n4) return;
    float4 v = ((const float4*)in)[i];
    __nv_bfloat16 h0 = __float2bfloat16(v.x), h1 = __float2bfloat16(v.y);
    __nv_bfloat16 h2 = __float2bfloat16(v.z), h3 = __float2bfloat16(v.w);
    __nv_bfloat162 hh0 = {h0, h1}, hh1 = {h2, h3};
    ((__nv_bfloat162*)hi)[i * 2 + 0] = hh0;
    ((__nv_bfloat162*)hi)[i * 2 + 1] = hh1;
    __nv_bfloat162 ll0 = {__float2bfloat16(v.x - __bfloat162float(h0)),
                          __float2bfloat16(v.y - __bfloat162float(h1))};
    __nv_bfloat162 ll1 = {__float2bfloat16(v.z - __bfloat162float(h2)),
                          __float2bfloat16(v.w - __bfloat162float(h3))};
    ((__nv_bfloat162*)lo)[i * 2 + 0] = ll0;
    ((__nv_bfloat162*)lo)[i * 2 + 1] = ll1;
}

// ---------------- transpose (b,d,l)->(b,l,d) + split ----------------
__global__ void k_split_T()
{
    __shared__ float tile[32][33];
    int l0 = blockIdx.x * 32, d0 = blockIdx.y * 32, b = blockIdx.z;
    int tx = threadIdx.x, ty = threadIdx.y;
#pragma unroll
    for (int k = 0; k < 4; k++)
        tile[ty + k * 8][tx] = g_g[((size_t)b * DD + d0 + ty + k * 8) * LL + l0 + tx];
    __syncthreads();
#pragma unroll
    for (int k = 0; k < 4; k++) {
        float v = tile[tx][ty + k * 8];
        size_t o = ((size_t)b * LL + l0 + ty + k * 8) * DD + d0 + tx;
        __nv_bfloat16 h = __float2bfloat16(v);
        g_gh[o] = h;
        g_gl[o] = __float2bfloat16(v - __bfloat162float(h));
    }
}

// ---------------- split-bf16 mma.sync GEMM (128x128 tiles, K=2048) ----------------
// mode 0: in_proj -> g_u transposed (b,c,l) layout
// mode 1: out_proj -> Out row-major (m,2048)
__global__ __launch_bounds__(256, 1)
void k_gemm_tc(const __nv_bfloat16* __restrict__ Ah, const __nv_bfloat16* __restrict__ Al,
               const __nv_bfloat16* __restrict__ Bh, const __nv_bfloat16* __restrict__ Bl,
               const float* __restrict__ bias, float* __restrict__ Out, int mode)
{
    extern __shared__ __align__(128) unsigned char dsm[];
    const uint32_t sb = smem_u32(dsm);
    const int tid  = threadIdx.x;
    const int lane = tid & 31;
    const int wid  = tid >> 5;
    const int wm   = wid >> 2;         // 0..1 -> m offset 64
    const int wn   = wid & 3;          // 0..3 -> n offset 32
    const int m0 = blockIdx.y * Bb_M;
    const int n0 = blockIdx.x * Bb_N;

    // ---- cp.async thread mapping: per matrix 512 16B chunks; this thread does 2 ----
    int id0 = tid, id1 = tid + 256;
    int row0 = id0 >> 2, c0 = id0 & 3;
    int row1 = id1 >> 2, c1 = id1 & 3;
    uint32_t so0 = swz((uint32_t)(row0 * 64 + c0 * 16));
    uint32_t so1 = swz((uint32_t)(row1 * 64 + c1 * 16));
    const __nv_bfloat16* pAh = Ah + (size_t)(m0 + row0) * KDIM + c0 * 8;
    const __nv_bfloat16* pAl = Al + (size_t)(m0 + row0) * KDIM + c0 * 8;
    const __nv_bfloat16* pBh = Bh + (size_t)(n0 + row0) * KDIM + c0 * 8;
    const __nv_bfloat16* pBl = Bl + (size_t)(n0 + row0) * KDIM + c0 * 8;
    const __nv_bfloat16* qAh = Ah + (size_t)(m0 + row1) * KDIM + c1 * 8;
    const __nv_bfloat16* qAl = Al + (size_t)(m0 + row1) * KDIM + c1 * 8;
    const __nv_bfloat16* qBh = Bh + (size_t)(n0 + row1) * KDIM + c1 * 8;
    const __nv_bfloat16* qBl = Bl + (size_t)(n0 + row1) * KDIM + c1 * 8;

#define LOADST(st, k0) do {                                                  \
        uint32_t base = sb + (uint32_t)(st) * STAGE_BYTES;                   \
        cpa16(base + so0,                 pAh + (k0));                       \
        cpa16(base + so1,                 qAh + (k0));                       \
        cpa16(base + MAT_BYTES + so0,     pAl + (k0));                       \
        cpa16(base + MAT_BYTES + so1,     qAl + (k0));                       \
        cpa16(base + 2 * MAT_BYTES + so0, pBh + (k0));                       \
        cpa16(base + 2 * MAT_BYTES + so1, qBh + (k0));                       \
        cpa16(base + 3 * MAT_BYTES + so0, pBl + (k0));                       \
        cpa16(base + 3 * MAT_BYTES + so1, qBl + (k0));                       \
        CPA_COMMIT();                                                        \
    } while (0)

    // ---- ldmatrix lane offsets (loop-invariant, pre-swizzled) ----
    uint32_t aoffs[4][2], boffs[4];
    {
        int ra = lane & 15, ka = (lane >> 4) * 16;
        int rb = lane & 7,  kb = (lane >> 3) * 16;
#pragma unroll
        for (int mi = 0; mi < 4; mi++)
#pragma unroll
            for (int s = 0; s < 2; s++)
                aoffs[mi][s] = swz((uint32_t)((wm * 64 + mi * 16 + ra) * 64 + s * 32 + ka));
#pragma unroll
        for (int ni = 0; ni < 4; ni++)
            boffs[ni] = swz((uint32_t)((wn * 32 + ni * 8 + rb) * 64 + kb));
    }

    float acc[4][4][4];
#pragma unroll
    for (int mi = 0; mi < 4; mi++)
#pragma unroll
        for (int ni = 0; ni < 4; ni++)
#pragma unroll
            for (int r = 0; r < 4; r++) acc[mi][ni][r] = 0.f;

    LOADST(0, 0);
    LOADST(1, Bb_K);

    for (int i = 0; i < NCHUNK; i++) {
        if (i + 2 < NCHUNK) LOADST((i + 2) % 3, (i + 2) * Bb_K);
        if (i + 2 < NCHUNK)      { CPA_WAIT2(); }
        else if (i + 1 < NCHUNK) { CPA_WAIT1(); }
        else                     { CPA_WAIT0(); }
        __syncthreads();

        uint32_t base = sb + (uint32_t)(i % 3) * STAGE_BYTES;
        uint32_t bh[4][4], bl[4][4];
#pragma unroll
        for (int ni = 0; ni < 4; ni++) {
            LDX4(bh[ni], base + 2 * MAT_BYTES + boffs[ni]);
            LDX4(bl[ni], base + 3 * MAT_BYTES + boffs[ni]);
        }
#pragma unroll
        for (int s = 0; s < 2; s++) {
            uint32_t ah[4][4], al[4][4];
#pragma unroll
            for (int mi = 0; mi < 4; mi++) {
                LDX4(ah[mi], base + aoffs[mi][s]);
                LDX4(al[mi], base + MAT_BYTES + aoffs[mi][s]);
            }
#pragma unroll
            for (int mi = 0; mi < 4; mi++)
#pragma unroll
                for (int ni = 0; ni < 4; ni++) {
                    MMA16816(acc[mi][ni], ah[mi], bh[ni][2 * s], bh[ni][2 * s + 1]);
                    MMA16816(acc[mi][ni], ah[mi], bl[ni][2 * s], bl[ni][2 * s + 1]);
                    MMA16816(acc[mi][ni], al[mi], bh[ni][2 * s], bh[ni][2 * s + 1]);
                }
        }
        __syncthreads();
    }
#undef LOADST

    // ---- epilogue: stage tile in smem for coalesced global stores ----
    float* ep = (float*)dsm;           // 128 rows x 132 floats = 67584 B
    const int r  = lane >> 2;
    const int cc = 2 * (lane & 3);
#pragma unroll
    for (int mi = 0; mi < 4; mi++)
#pragma unroll
        for (int ni = 0; ni < 4; ni++) {
            int mloc = wm * 64 + mi * 16 + r;
            int nloc = wn * 32 + ni * 8 + cc;
            const float* a = acc[mi][ni];
            if (mode == 0) {
                ep[nloc * 132 + mloc]           = a[0];
                ep[(nloc + 1) * 132 + mloc]     = a[1];
                ep[nloc * 132 + mloc + 8]       = a[2];
                ep[(nloc + 1) * 132 + mloc + 8] = a[3];
            } else {
                ep[mloc * 132 + nloc]           = a[0];
                ep[mloc * 132 + nloc + 1]       = a[1];
                ep[(mloc + 8) * 132 + nloc]     = a[2];
                ep[(mloc + 8) * 132 + nloc + 1] = a[3];
            }
        }
    __syncthreads();

    const int erow = tid >> 1;
    const int half = tid & 1;
    const float* src = ep + erow * 132 + half * 64;
    if (mode == 0) {
        const int b  = m0 >> 12;
        const int l0 = (m0 & (LL - 1)) + half * 64;
        const float bi = bias[n0 + erow];
        float* dst = g_u + ((size_t)b * N3 + n0 + erow) * LL + l0;
#pragma unroll
        for (int j = 0; j < 16; j++) {
            float4 v = *(const float4*)(src + j * 4);
            v.x += bi; v.y += bi; v.z += bi; v.w += bi;
            *(float4*)(dst + j * 4) = v;
        }
    } else {
        float* dst = Out + (size_t)(m0 + erow) * 2048 + n0 + half * 64;
        const float* bp = bias + n0 + half * 64;
#pragma unroll
        for (int j = 0; j < 16; j++) {
            float4 v = *(const float4*)(src + j * 4);
            float4 bb = *(const float4*)(bp + j * 4);
            v.x += bb.x; v.y += bb.y; v.z += bb.z; v.w += bb.w;
            *(float4*)(dst + j * 4) = v;
        }
    }
}

// ---------------- depthwise short conv (K=3, causal) + split + gate v*x1 ----------------
__global__ void k_shortconv(const float* __restrict__ sw, const float* __restrict__ sb)
{
    int l = blockIdx.x * blockDim.x + threadIdx.x;
    int d = blockIdx.y;
    int b = blockIdx.z;
    if (l >= LL) return;
    float r[3];
#pragma unroll
    for (int part = 0; part < 3; part++) {
        int cc = part * DD + d;
        const float* u = g_u + ((size_t)b * N3 + cc) * LL;
        float w0 = sw[cc * 3 + 0], w1 = sw[cc * 3 + 1], w2 = sw[cc * 3 + 2];
        float acc = sb[cc] + w2 * u[l];
        if (l >= 1) acc += w1 * u[l - 1];
        if (l >= 2) acc += w0 * u[l - 2];
        r[part] = acc;
    }
    size_t o = ((size_t)b * DD + d) * LL + l;
    g_x0[o] = r[0];
    g_v[o]  = r[2] * r[1];
}

// ---------------- filter MLP features h(l) ----------------
__global__ __launch_bounds__(256)
void k_filter_h(const float* __restrict__ w0, const float* __restrict__ b0,
                const float* __restrict__ fr,
                const float* __restrict__ w1, const float* __restrict__ b1,
                const float* __restrict__ w2, const float* __restrict__ b2)
{
    __shared__ float hb[2][4][ORD];
    int o  = threadIdx.x & 63;
    int sl = threadIdx.x >> 6;
    int l  = blockIdx.x * 4 + sl;

    float t    = (float)l * (1.0f / (LL - 1));
    float wang = 6.28318530717958647692f * (float)l * (1.0f / LL);
    float ang  = 1e-4f * wang;
    float z0 = t, z1 = cosf(ang), z2 = -sinf(ang);
    float f = fr[o];

    float h = sinf(f * (w0[o * 3 + 0] * z0 + w0[o * 3 + 1] * z1 + w0[o * 3 + 2] * z2 + b0[o]));
    hb[0][sl][o] = h;
    __syncthreads();

    float acc = b1[o];
#pragma unroll
    for (int j = 0; j < ORD; j++) acc += w1[o * ORD + j] * hb[0][sl][j];
    h = sinf(f * acc);
    hb[1][sl][o] = h;
    __syncthreads();

    acc = b2[o];
#pragma unroll
    for (int j = 0; j < ORD; j++) acc += w2[o * ORD + j] * hb[1][sl][j];
    h = sinf(f * acc);
    g_h[(size_t)l * ORD + o] = h;
}

// ---------------- filter k(d,l) ----------------
#define MIN_DECAY (-3.0701134573253937f)
#define MAX_DECAY (-15.350567286626969f)
__global__ __launch_bounds__(256)
void k_filter_k(const float* __restrict__ W3)
{
    __shared__ float hs[64][65];
    __shared__ float ws[64][64];
    int l0 = blockIdx.x * 64;
    int d0 = blockIdx.y * 64;
    for (int i = threadIdx.x; i < 64 * 64; i += 256) {
        int r = i >> 6, cidx = i & 63;
        hs[r][cidx] = g_h[(size_t)(l0 + r) * ORD + cidx];
        ws[r][cidx] = W3[(size_t)(d0 + r) * ORD + cidx];
    }
    __syncthreads();
    for (int i = threadIdx.x; i < 64 * 64; i += 256) {
        int ll = i & 63;
        int dd = i >> 6;
        float acc = 0.f;
#pragma unroll
        for (int j = 0; j < ORD; j++) acc += ws[dd][j] * hs[ll][j];
        int d = d0 + dd, l = l0 + ll;
        float delta = MIN_DECAY + (MAX_DECAY - MIN_DECAY) * (float)d * (1.0f / (DD - 1));
        float decay = expf(-((float)l * (1.0f / (LL - 1))) * fabsf(delta));
        g_k[(size_t)d * LL + l] = acc * decay;
    }
}

// ---------------- shared-memory radix-2 FFT (N=8192) ----------------
__device__ __forceinline__ void fft8192_shared(float2* sm, const float2* stw, bool inverse)
{
    const int tid = threadIdx.x;
    const int nt  = blockDim.x;
    for (int j = tid; j < NFFT; j += nt) {
        int r = __brev(j) >> 19;
        if (r > j) { float2 tmp = sm[j]; sm[j] = sm[r]; sm[r] = tmp; }
    }
    __syncthreads();
#pragma unroll 1
    for (int s = 1; s <= 13; s++) {
        const int half   = 1 << (s - 1);
        const int tshift = 13 - s;
        for (int t = tid; t < HALF_N; t += nt) {
            int j = t & (half - 1);
            int base = ((t >> (s - 1)) << s) + j;
            float2 w = stw[j << tshift];
            float wy = inverse ? -w.y : w.y;
            float2 u = sm[base];
            float2 v = sm[base + half];
            float wvx = w.x * v.x - wy * v.y;
            float wvy = w.x * v.y + wy * v.x;
            sm[base]        = make_float2(u.x + wvx, u.y + wvy);
            sm[base + half] = make_float2(u.x - wvx, u.y - wvy);
        }
        __syncthreads();
    }
}

extern __shared__ float2 dynsm[];

// ---------------- FFT of filter rows: pack 2 real rows per complex FFT ----------------
__global__ void k_fft_k()
{
    float2* sm  = dynsm;
    float2* stw = dynsm + NFFT;
    const int d  = blockIdx.x;          // 0..1023
    const int d2 = d + DD / 2;
    const int tid = threadIdx.x;
    for (int j = tid; j < HALF_N; j += blockDim.x) stw[j] = g_tw[j];
    const float* k0 = g_k + (size_t)d  * LL;
    const float* k1 = g_k + (size_t)d2 * LL;
    for (int j = tid; j < NFFT; j += blockDim.x)
        sm[j] = (j < LL) ? make_float2(k0[j], k1[j]) : make_float2(0.f, 0.f);
    __syncthreads();
    fft8192_shared(sm, stw, false);
    float2* kfa = g_kf + (size_t)d  * KFW;
    float2* kfb = g_kf + (size_t)d2 * KFW;
    for (int t = tid; t <= HALF_N; t += blockDim.x) {
        int j2 = (NFFT - t) & (NFFT - 1);
        float2 Zj = sm[t], Zk = sm[j2];
        kfa[t] = make_float2(0.5f * (Zj.x + Zk.x), 0.5f * (Zj.y - Zk.y));
        kfb[t] = make_float2(0.5f * (Zj.y + Zk.y), -0.5f * (Zj.x - Zk.x));
    }
}

// ---------------- FFT conv: pack both batches (share K spectrum) ----------------
__global__ void k_fftconv(const float* __restrict__ fbias)
{
    float2* sm  = dynsm;
    float2* stw = dynsm + NFFT;
    const int d   = blockIdx.x;         // 0..2047
    const int tid = threadIdx.x;
    const float* v0 = g_v + (size_t)d * LL;
    const float* v1 = g_v + ((size_t)DD + d) * LL;

    for (int j = tid; j < HALF_N; j += blockDim.x) stw[j] = g_tw[j];
    for (int j = tid; j < NFFT; j += blockDim.x)
        sm[j] = (j < LL) ? make_float2(v0[j], v1[j]) : make_float2(0.f, 0.f);
    __syncthreads();
    fft8192_shared(sm, stw, false);

    const float2* kf = g_kf + (size_t)d * KFW;
    for (int t = tid; t <= HALF_N; t += blockDim.x) {
        int j2 = (NFFT - t) & (NFFT - 1);
        float2 Zj = sm[t], Zk = sm[j2];
        float2 V0 = make_float2(0.5f * (Zj.x + Zk.x), 0.5f * (Zj.y - Zk.y));
        float2 V1 = make_float2(0.5f * (Zj.y + Zk.y), -0.5f * (Zj.x - Zk.x));
        float2 K  = kf[t];
        float2 Y0 = make_float2(V0.x * K.x - V0.y * K.y, V0.x * K.y + V0.y * K.x);
        float2 Y1 = make_float2(V1.x * K.x - V1.y * K.y, V1.x * K.y + V1.y * K.x);
        sm[t]  = make_float2(Y0.x - Y1.y,  Y0.y + Y1.x);
        sm[j2] = make_float2(Y0.x + Y1.y, -Y0.y + Y1.x);
    }
    __syncthreads();
    fft8192_shared(sm, stw, true);

    const float bi = fbias[d];
    const float* x00 = g_x0 + (size_t)d * LL;
    const float* x01 = g_x0 + ((size_t)DD + d) * LL;
    float* gg0 = g_g + (size_t)d * LL;
    float* gg1 = g_g + ((size_t)DD + d) * LL;
    const float inv = 1.0f / (float)NFFT;
    for (int j = tid; j < LL; j += blockDim.x) {
        float2 y = sm[j];
        gg0[j] = (y.x * inv + v0[j] * bi) * x00[j];
        gg1[j] = (y.y * inv + v1[j] * bi) * x01[j];
    }
}

// ---------------- launch ----------------
extern "C" void kernel_launch(void* const* d_in, const int* in_sizes, int n_in,
                              void* d_out, int out_size)
{
    const float* x    = (const float*)d_in[0];
    const float* iw   = (const float*)d_in[1];
    const float* ib   = (const float*)d_in[2];
    const float* sw   = (const float*)d_in[3];
    const float* sb   = (const float*)d_in[4];
    const float* w0   = (const float*)d_in[5];
    const float* b0   = (const float*)d_in[6];
    const float* fr   = (const float*)d_in[7];
    const float* w1   = (const float*)d_in[8];
    const float* b1   = (const float*)d_in[9];
    const float* w2   = (const float*)d_in[10];
    const float* b2   = (const float*)d_in[11];
    const float* w3   = (const float*)d_in[12];
    const float* fb   = (const float*)d_in[13];
    const float* ow   = (const float*)d_in[14];
    const float* ob   = (const float*)d_in[15];
    float* out = (float*)d_out;

    const int fft_smem = (NFFT + HALF_N) * sizeof(float2);   // 96 KB
    (void)cudaFuncSetAttribute(k_fft_k,   cudaFuncAttributeMaxDynamicSharedMemorySize, fft_smem);
    (void)cudaFuncSetAttribute(k_fftconv, cudaFuncAttributeMaxDynamicSharedMemorySize, fft_smem);
    (void)cudaFuncSetAttribute(k_gemm_tc, cudaFuncAttributeMaxDynamicSharedMemorySize, GEMM_SMEM);

    __nv_bfloat16 *xh, *xl, *wih, *wil, *gh, *gl, *woh, *wol;
    cudaGetSymbolAddress((void**)&xh,  g_xh);  cudaGetSymbolAddress((void**)&xl,  g_xl);
    cudaGetSymbolAddress((void**)&wih, g_wih); cudaGetSymbolAddress((void**)&wil, g_wil);
    cudaGetSymbolAddress((void**)&gh,  g_gh);  cudaGetSymbolAddress((void**)&gl,  g_gl);
    cudaGetSymbolAddress((void**)&woh, g_woh); cudaGetSymbolAddress((void**)&wol, g_wol);

    // bf16 hi/lo splits of GEMM operands
    int n4;
    n4 = (MROWS * KDIM) / 4;  k_split<<<(n4 + 255) / 256, 256>>>(x,  xh,  xl,  n4);
    n4 = (N3 * KDIM) / 4;     k_split<<<(n4 + 255) / 256, 256>>>(iw, wih, wil, n4);
    n4 = (DD * KDIM) / 4;     k_split<<<(n4 + 255) / 256, 256>>>(ow, woh, wol, n4);

    // filter path
    k_twiddle<<<8, 512>>>();
    k_filter_h<<<LL / 4, 256>>>(w0, b0, fr, w1, b1, w2, b2);
    k_filter_k<<<dim3(LL / 64, DD / 64), 256>>>(w3);
    k_fft_k<<<DD / 2, 512, fft_smem>>>();

    // data path
    k_gemm_tc<<<dim3(N3 / 128, MROWS / 128), 256, GEMM_SMEM>>>(xh, xl, wih, wil, ib, nullptr, 0);
    k_shortconv<<<dim3(LL / 256, DD, BB), 256>>>(sw, sb);
    k_fftconv<<<DD, 512, fft_smem>>>(fb);
    k_split_T<<<dim3(LL / 32, DD / 32, BB), dim3(32, 8)>>>();
    k_gemm_tc<<<dim3(DD / 128, MROWS / 128), 256, GEMM_SMEM>>>(gh, gl, woh, wol, ob, out, 1);
}

// round 6
// speedup vs baseline: 4.8355x; 1.2463x over previous
#include <cuda_runtime.h>
#include <cuda_bf16.h>
#include <cstdint>

// ---------------- problem constants ----------------
#define BB      2
#define DD      2048
#define LL      4096
#define N3      6144          // 3*D
#define NFFT    8192          // 2*L
#define ORD     64            // filter order
#define KDIM    2048          // GEMM K (both GEMMs)
#define MROWS   8192          // GEMM M (B*L)

// GEMM tiling
#define Bb_K 32
#define NCHUNK (KDIM / Bb_K)          // 64
#define MAT_BYTES  (128 * 32 * 2)     // 8192 per matrix per stage
#define STAGE_BYTES (4 * MAT_BYTES)   // 32768
#define GEMM_SMEM  (3 * STAGE_BYTES)  // 98304

// FFT smem layout (floats), padded idx = i + (i>>5)
#define PD(i) ((i) + ((i) >> 5))
#define XPAD 8448
#define TPAD 2112
#define FFT_SMEM ((2 * XPAD + 2 * TPAD) * 4)   // 84480 bytes

// ---------------- scratch (device globals) ----------------
__device__ float  g_u [(size_t)BB * N3 * LL];     // in_proj output, (b, c, l)
__device__ float  g_k [(size_t)DD * LL];          // filter k, (d, l)
__device__ float  g_h [(size_t)LL * ORD];         // MLP features h, (l, o)
__device__ float2 g_kf[(size_t)DD * NFFT];        // K full spectra (DIF order)
__device__ float2 g_tw2[2048];                    // twiddles e^{-2pi i m/8192}, m<2048

// bf16 split operands
__device__ __nv_bfloat16 g_xh [(size_t)MROWS * KDIM];
__device__ __nv_bfloat16 g_xl [(size_t)MROWS * KDIM];
__device__ __nv_bfloat16 g_wih[(size_t)N3 * KDIM];
__device__ __nv_bfloat16 g_wil[(size_t)N3 * KDIM];
__device__ __nv_bfloat16 g_gh [(size_t)BB * DD * LL];   // gated output, (b,d,l)
__device__ __nv_bfloat16 g_gl [(size_t)BB * DD * LL];
__device__ __nv_bfloat16 g_woh[(size_t)DD * KDIM];
__device__ __nv_bfloat16 g_wol[(size_t)DD * KDIM];

// ---------------- PTX helpers ----------------
__device__ __forceinline__ uint32_t smem_u32(const void* p) {
    uint32_t a;
    asm("{ .reg .u64 t; cvta.to.shared.u64 t, %1; cvt.u32.u64 %0, t; }" : "=r"(a) : "l"(p));
    return a;
}
__device__ __forceinline__ void cpa16(uint32_t dst, const void* src) {
    asm volatile("cp.async.cg.shared.global [%0], [%1], 16;" :: "r"(dst), "l"(src) : "memory");
}
#define CPA_COMMIT() asm volatile("cp.async.commit_group;" ::: "memory")
#define CPA_WAIT2()  asm volatile("cp.async.wait_group 2;" ::: "memory")
#define CPA_WAIT1()  asm volatile("cp.async.wait_group 1;" ::: "memory")
#define CPA_WAIT0()  asm volatile("cp.async.wait_group 0;" ::: "memory")

#define LDX4(r, addr) \
    asm volatile("ldmatrix.sync.aligned.m8n8.x4.shared.b16 {%0,%1,%2,%3}, [%4];" \
        : "=r"((r)[0]), "=r"((r)[1]), "=r"((r)[2]), "=r"((r)[3]) : "r"(addr))
#define LDX4T(r, addr) \
    asm volatile("ldmatrix.sync.aligned.m8n8.x4.trans.shared.b16 {%0,%1,%2,%3}, [%4];" \
        : "=r"((r)[0]), "=r"((r)[1]), "=r"((r)[2]), "=r"((r)[3]) : "r"(addr))

#define MMA16816(d, a, b0, b1) \
    asm volatile("mma.sync.aligned.m16n8k16.row.col.f32.bf16.bf16.f32 " \
        "{%0,%1,%2,%3}, {%4,%5,%6,%7}, {%8,%9}, {%0,%1,%2,%3};" \
        : "+f"((d)[0]), "+f"((d)[1]), "+f"((d)[2]), "+f"((d)[3]) \
        : "r"((a)[0]), "r"((a)[1]), "r"((a)[2]), "r"((a)[3]), "r"(b0), "r"(b1))

__device__ __forceinline__ uint32_t swz(uint32_t off) {
    return off ^ ((off >> 3) & 0x30u);
}

// ---------------- twiddle table ----------------
__global__ void k_twiddle() {
    int j = blockIdx.x * blockDim.x + threadIdx.x;
    if (j < 2048) {
        double a = -2.0 * 3.14159265358979323846 * (double)j / (double)NFFT;
        g_tw2[j] = make_float2((float)cos(a), (float)sin(a));
    }
}

// ---------------- fp32 -> bf16 hi/lo split ----------------
__global__ void k_split(const float* __restrict__ in, __nv_bfloat16* __restrict__ hi,
                        __nv_bfloat16* __restrict__ lo, int n4)
{
    int i = blockIdx.x * blockDim.x + threadIdx.x;
    if (i >= n4) return;
    float4 v = ((const float4*)in)[i];
    __nv_bfloat16 h0 = __float2bfloat16(v.x), h1 = __float2bfloat16(v.y);
    __nv_bfloat16 h2 = __float2bfloat16(v.z), h3 = __float2bfloat16(v.w);
    __nv_bfloat162 hh0 = {h0, h1}, hh1 = {h2, h3};
    ((__nv_bfloat162*)hi)[i * 2 + 0] = hh0;
    ((__nv_bfloat162*)hi)[i * 2 + 1] = hh1;
    __nv_bfloat162 ll0 = {__float2bfloat16(v.x - __bfloat162float(h0)),
                          __float2bfloat16(v.y - __bfloat162float(h1))};
    __nv_bfloat162 ll1 = {__float2bfloat16(v.z - __bfloat162float(h2)),
                          __float2bfloat16(v.w - __bfloat162float(h3))};
    ((__nv_bfloat162*)lo)[i * 2 + 0] = ll0;
    ((__nv_bfloat162*)lo)[i * 2 + 1] = ll1;
}

// ================= GEMM 1: in_proj (A row-major (m,k)) =================
__global__ __launch_bounds__(256, 1)
void k_gemm_in(const __nv_bfloat16* __restrict__ Ah, const __nv_bfloat16* __restrict__ Al,
               const __nv_bfloat16* __restrict__ Bh, const __nv_bfloat16* __restrict__ Bl,
               const float* __restrict__ bias)
{
    extern __shared__ __align__(128) unsigned char dsm[];
    const uint32_t sb = smem_u32(dsm);
    const int tid  = threadIdx.x;
    const int lane = tid & 31;
    const int wid  = tid >> 5;
    const int wm   = wid >> 2;
    const int wn   = wid & 3;
    const int m0 = blockIdx.y * 128;
    const int n0 = blockIdx.x * 128;

    int row0 = tid >> 1 >> 1, c0 = tid & 3;           // tid>>2, tid&3
    row0 = tid >> 2;
    int row1 = (tid + 256) >> 2, c1 = (tid + 256) & 3;
    uint32_t so0 = swz((uint32_t)(row0 * 64 + c0 * 16));
    uint32_t so1 = swz((uint32_t)(row1 * 64 + c1 * 16));
    const __nv_bfloat16* pAh = Ah + (size_t)(m0 + row0) * KDIM + c0 * 8;
    const __nv_bfloat16* pAl = Al + (size_t)(m0 + row0) * KDIM + c0 * 8;
    const __nv_bfloat16* pBh = Bh + (size_t)(n0 + row0) * KDIM + c0 * 8;
    const __nv_bfloat16* pBl = Bl + (size_t)(n0 + row0) * KDIM + c0 * 8;
    const __nv_bfloat16* qAh = Ah + (size_t)(m0 + row1) * KDIM + c1 * 8;
    const __nv_bfloat16* qAl = Al + (size_t)(m0 + row1) * KDIM + c1 * 8;
    const __nv_bfloat16* qBh = Bh + (size_t)(n0 + row1) * KDIM + c1 * 8;
    const __nv_bfloat16* qBl = Bl + (size_t)(n0 + row1) * KDIM + c1 * 8;

#define LOADST(st, k0) do {                                                  \
        uint32_t base = sb + (uint32_t)(st) * STAGE_BYTES;                   \
        cpa16(base + so0,                 pAh + (k0));                       \
        cpa16(base + so1,                 qAh + (k0));                       \
        cpa16(base + MAT_BYTES + so0,     pAl + (k0));                       \
        cpa16(base + MAT_BYTES + so1,     qAl + (k0));                       \
        cpa16(base + 2 * MAT_BYTES + so0, pBh + (k0));                       \
        cpa16(base + 2 * MAT_BYTES + so1, qBh + (k0));                       \
        cpa16(base + 3 * MAT_BYTES + so0, pBl + (k0));                       \
        cpa16(base + 3 * MAT_BYTES + so1, qBl + (k0));                       \
        CPA_COMMIT();                                                        \
    } while (0)

    uint32_t aoffs[4][2], boffs[4];
    {
        int ra = lane & 15, ka = (lane >> 4) * 16;
        int rb = lane & 7,  kb = (lane >> 3) * 16;
#pragma unroll
        for (int mi = 0; mi < 4; mi++)
#pragma unroll
            for (int s = 0; s < 2; s++)
                aoffs[mi][s] = swz((uint32_t)((wm * 64 + mi * 16 + ra) * 64 + s * 32 + ka));
#pragma unroll
        for (int ni = 0; ni < 4; ni++)
            boffs[ni] = swz((uint32_t)((wn * 32 + ni * 8 + rb) * 64 + kb));
    }

    float acc[4][4][4];
#pragma unroll
    for (int mi = 0; mi < 4; mi++)
#pragma unroll
        for (int ni = 0; ni < 4; ni++)
#pragma unroll
            for (int r = 0; r < 4; r++) acc[mi][ni][r] = 0.f;

    LOADST(0, 0);
    LOADST(1, Bb_K);

    for (int i = 0; i < NCHUNK; i++) {
        if (i + 2 < NCHUNK) LOADST((i + 2) % 3, (i + 2) * Bb_K);
        if (i + 2 < NCHUNK)      { CPA_WAIT2(); }
        else if (i + 1 < NCHUNK) { CPA_WAIT1(); }
        else                     { CPA_WAIT0(); }
        __syncthreads();

        uint32_t base = sb + (uint32_t)(i % 3) * STAGE_BYTES;
        uint32_t bh[4][4], bl[4][4];
#pragma unroll
        for (int ni = 0; ni < 4; ni++) {
            LDX4(bh[ni], base + 2 * MAT_BYTES + boffs[ni]);
            LDX4(bl[ni], base + 3 * MAT_BYTES + boffs[ni]);
        }
#pragma unroll
        for (int s = 0; s < 2; s++) {
            uint32_t ah[4][4], al[4][4];
#pragma unroll
            for (int mi = 0; mi < 4; mi++) {
                LDX4(ah[mi], base + aoffs[mi][s]);
                LDX4(al[mi], base + MAT_BYTES + aoffs[mi][s]);
            }
#pragma unroll
            for (int mi = 0; mi < 4; mi++)
#pragma unroll
                for (int ni = 0; ni < 4; ni++) {
                    MMA16816(acc[mi][ni], ah[mi], bh[ni][2 * s], bh[ni][2 * s + 1]);
                    MMA16816(acc[mi][ni], ah[mi], bl[ni][2 * s], bl[ni][2 * s + 1]);
                    MMA16816(acc[mi][ni], al[mi], bh[ni][2 * s], bh[ni][2 * s + 1]);
                }
        }
        __syncthreads();
    }
#undef LOADST

    // epilogue: transpose via smem, store (b,c,l)
    float* ep = (float*)dsm;
    const int r  = lane >> 2;
    const int cc = 2 * (lane & 3);
#pragma unroll
    for (int mi = 0; mi < 4; mi++)
#pragma unroll
        for (int ni = 0; ni < 4; ni++) {
            int mloc = wm * 64 + mi * 16 + r;
            int nloc = wn * 32 + ni * 8 + cc;
            const float* a = acc[mi][ni];
            ep[nloc * 132 + mloc]           = a[0];
            ep[(nloc + 1) * 132 + mloc]     = a[1];
            ep[nloc * 132 + mloc + 8]       = a[2];
            ep[(nloc + 1) * 132 + mloc + 8] = a[3];
        }
    __syncthreads();

    const int erow = tid >> 1;
    const int half = tid & 1;
    const float* src = ep + erow * 132 + half * 64;
    const int b  = m0 >> 12;
    const int l0 = (m0 & (LL - 1)) + half * 64;
    const float bi = bias[n0 + erow];
    float* dst = g_u + ((size_t)b * N3 + n0 + erow) * LL + l0;
#pragma unroll
    for (int j = 0; j < 16; j++) {
        float4 v = *(const float4*)(src + j * 4);
        v.x += bi; v.y += bi; v.z += bi; v.w += bi;
        *(float4*)(dst + j * 4) = v;
    }
}

// ================= GEMM 2: out_proj (A from (b,d,l) via ldmatrix.trans) =================
__global__ __launch_bounds__(256, 1)
void k_gemm_out(const __nv_bfloat16* __restrict__ Ah, const __nv_bfloat16* __restrict__ Al,
                const __nv_bfloat16* __restrict__ Bh, const __nv_bfloat16* __restrict__ Bl,
                const float* __restrict__ bias, float* __restrict__ Out)
{
    extern __shared__ __align__(128) unsigned char dsm[];
    const uint32_t sb = smem_u32(dsm);
    const int tid  = threadIdx.x;
    const int lane = tid & 31;
    const int wid  = tid >> 5;
    const int wm   = wid >> 2;
    const int wn   = wid & 3;
    const int m0 = blockIdx.y * 128;
    const int n0 = blockIdx.x * 128;
    const int bb = m0 >> 12;
    const int l0 = m0 & (LL - 1);

    // A (trans) cp.async mapping: tile [32 k][128 m]; chunk (r,c): r=0..31, c=0..15
    int rA = tid >> 4, cA = tid & 15;
    uint32_t soA0 = (uint32_t)(rA * 256 + ((cA ^ (rA & 7)) << 4));
    uint32_t soA1 = soA0 + 4096;   // rows +16, same xor
    const __nv_bfloat16* pAh0 = Ah + ((size_t)bb * DD + rA) * LL + l0 + cA * 8;
    const __nv_bfloat16* pAl0 = Al + ((size_t)bb * DD + rA) * LL + l0 + cA * 8;
    const __nv_bfloat16* pAh1 = pAh0 + (size_t)16 * LL;
    const __nv_bfloat16* pAl1 = pAl0 + (size_t)16 * LL;

    // B mapping (row-major (n,k)) as in k_gemm_in
    int rowB0 = tid >> 2, cB0 = tid & 3;
    int rowB1 = (tid + 256) >> 2, cB1 = (tid + 256) & 3;
    uint32_t soB0 = swz((uint32_t)(rowB0 * 64 + cB0 * 16));
    uint32_t soB1 = swz((uint32_t)(rowB1 * 64 + cB1 * 16));
    const __nv_bfloat16* pBh = Bh + (size_t)(n0 + rowB0) * KDIM + cB0 * 8;
    const __nv_bfloat16* pBl = Bl + (size_t)(n0 + rowB0) * KDIM + cB0 * 8;
    const __nv_bfloat16* qBh = Bh + (size_t)(n0 + rowB1) * KDIM + cB1 * 8;
    const __nv_bfloat16* qBl = Bl + (size_t)(n0 + rowB1) * KDIM + cB1 * 8;

#define LOADST2(st, ci) do {                                                   \
        uint32_t base = sb + (uint32_t)(st) * STAGE_BYTES;                     \
        size_t ko = (size_t)(ci) * Bb_K * LL;                                  \
        int kb = (ci) * Bb_K;                                                  \
        cpa16(base + soA0,                 pAh0 + ko);                         \
        cpa16(base + soA1,                 pAh1 + ko);                         \
        cpa16(base + MAT_BYTES + soA0,     pAl0 + ko);                         \
        cpa16(base + MAT_BYTES + soA1,     pAl1 + ko);                         \
        cpa16(base + 2 * MAT_BYTES + soB0, pBh + kb);                          \
        cpa16(base + 2 * MAT_BYTES + soB1, qBh + kb);                          \
        cpa16(base + 3 * MAT_BYTES + soB0, pBl + kb);                          \
        cpa16(base + 3 * MAT_BYTES + soB1, qBl + kb);                          \
        CPA_COMMIT();                                                          \
    } while (0)

    // ldmatrix.trans A offsets; B offsets standard
    uint32_t aoffT[4][2], boffs[4];
    {
        int kr = (lane & 7) + ((lane >> 4) << 3);
        int msub = ((lane >> 3) & 1) * 8;
        int rb = lane & 7, kb = (lane >> 3) * 16;
#pragma unroll
        for (int mi = 0; mi < 4; mi++)
#pragma unroll
            for (int s = 0; s < 2; s++) {
                int row = s * 16 + kr;
                int mcChunk = (wm * 64 + mi * 16 + msub) >> 3;
                aoffT[mi][s] = (uint32_t)(row * 256 + ((mcChunk ^ (row & 7)) << 4));
            }
#pragma unroll
        for (int ni = 0; ni < 4; ni++)
            boffs[ni] = swz((uint32_t)((wn * 32 + ni * 8 + rb) * 64 + kb));
    }

    float acc[4][4][4];
#pragma unroll
    for (int mi = 0; mi < 4; mi++)
#pragma unroll
        for (int ni = 0; ni < 4; ni++)
#pragma unroll
            for (int r = 0; r < 4; r++) acc[mi][ni][r] = 0.f;

    LOADST2(0, 0);
    LOADST2(1, 1);

    for (int i = 0; i < NCHUNK; i++) {
        if (i + 2 < NCHUNK) LOADST2((i + 2) % 3, i + 2);
        if (i + 2 < NCHUNK)      { CPA_WAIT2(); }
        else if (i + 1 < NCHUNK) { CPA_WAIT1(); }
        else                     { CPA_WAIT0(); }
        __syncthreads();

        uint32_t base = sb + (uint32_t)(i % 3) * STAGE_BYTES;
        uint32_t bh[4][4], bl[4][4];
#pragma unroll
        for (int ni = 0; ni < 4; ni++) {
            LDX4(bh[ni], base + 2 * MAT_BYTES + boffs[ni]);
            LDX4(bl[ni], base + 3 * MAT_BYTES + boffs[ni]);
        }
#pragma unroll
        for (int s = 0; s < 2; s++) {
            uint32_t ah[4][4], al[4][4];
#pragma unroll
            for (int mi = 0; mi < 4; mi++) {
                LDX4T(ah[mi], base + aoffT[mi][s]);
                LDX4T(al[mi], base + MAT_BYTES + aoffT[mi][s]);
            }
#pragma unroll
            for (int mi = 0; mi < 4; mi++)
#pragma unroll
                for (int ni = 0; ni < 4; ni++) {
                    MMA16816(acc[mi][ni], ah[mi], bh[ni][2 * s], bh[ni][2 * s + 1]);
                    MMA16816(acc[mi][ni], ah[mi], bl[ni][2 * s], bl[ni][2 * s + 1]);
                    MMA16816(acc[mi][ni], al[mi], bh[ni][2 * s], bh[ni][2 * s + 1]);
                }
        }
        __syncthreads();
    }
#undef LOADST2

    // epilogue: row-major store
    float* ep = (float*)dsm;
    const int r  = lane >> 2;
    const int cc = 2 * (lane & 3);
#pragma unroll
    for (int mi = 0; mi < 4; mi++)
#pragma unroll
        for (int ni = 0; ni < 4; ni++) {
            int mloc = wm * 64 + mi * 16 + r;
            int nloc = wn * 32 + ni * 8 + cc;
            const float* a = acc[mi][ni];
            ep[mloc * 132 + nloc]           = a[0];
            ep[mloc * 132 + nloc + 1]       = a[1];
            ep[(mloc + 8) * 132 + nloc]     = a[2];
            ep[(mloc + 8) * 132 + nloc + 1] = a[3];
        }
    __syncthreads();

    const int erow = tid >> 1;
    const int half = tid & 1;
    const float* src = ep + erow * 132 + half * 64;
    float* dst = Out + (size_t)(m0 + erow) * 2048 + n0 + half * 64;
    const float* bp = bias + n0 + half * 64;
#pragma unroll
    for (int j = 0; j < 16; j++) {
        float4 v = *(const float4*)(src + j * 4);
        float4 bv = *(const float4*)(bp + j * 4);
        v.x += bv.x; v.y += bv.y; v.z += bv.z; v.w += bv.w;
        *(float4*)(dst + j * 4) = v;
    }
}

// ---------------- filter MLP features h(l) ----------------
__global__ __launch_bounds__(256)
void k_filter_h(const float* __restrict__ w0, const float* __restrict__ b0,
                const float* __restrict__ fr,
                const float* __restrict__ w1, const float* __restrict__ b1,
                const float* __restrict__ w2, const float* __restrict__ b2)
{
    __shared__ float hb[2][4][ORD];
    int o  = threadIdx.x & 63;
    int sl = threadIdx.x >> 6;
    int l  = blockIdx.x * 4 + sl;

    float t    = (float)l * (1.0f / (LL - 1));
    float wang = 6.28318530717958647692f * (float)l * (1.0f / LL);
    float ang  = 1e-4f * wang;
    float z0 = t, z1 = cosf(ang), z2 = -sinf(ang);
    float f = fr[o];

    float h = sinf(f * (w0[o * 3 + 0] * z0 + w0[o * 3 + 1] * z1 + w0[o * 3 + 2] * z2 + b0[o]));
    hb[0][sl][o] = h;
    __syncthreads();

    float acc = b1[o];
#pragma unroll
    for (int j = 0; j < ORD; j++) acc += w1[o * ORD + j] * hb[0][sl][j];
    h = sinf(f * acc);
    hb[1][sl][o] = h;
    __syncthreads();

    acc = b2[o];
#pragma unroll
    for (int j = 0; j < ORD; j++) acc += w2[o * ORD + j] * hb[1][sl][j];
    h = sinf(f * acc);
    g_h[(size_t)l * ORD + o] = h;
}

// ---------------- filter k(d,l) ----------------
#define MIN_DECAY (-3.0701134573253937f)
#define MAX_DECAY (-15.350567286626969f)
__global__ __launch_bounds__(256)
void k_filter_k(const float* __restrict__ W3)
{
    __shared__ float hs[64][65];
    __shared__ float ws[64][64];
    int l0 = blockIdx.x * 64;
    int d0 = blockIdx.y * 64;
    for (int i = threadIdx.x; i < 64 * 64; i += 256) {
        int r = i >> 6, cidx = i & 63;
        hs[r][cidx] = g_h[(size_t)(l0 + r) * ORD + cidx];
        ws[r][cidx] = W3[(size_t)(d0 + r) * ORD + cidx];
    }
    __syncthreads();
    for (int i = threadIdx.x; i < 64 * 64; i += 256) {
        int ll = i & 63;
        int dd = i >> 6;
        float acc = 0.f;
#pragma unroll
        for (int j = 0; j < ORD; j++) acc += ws[dd][j] * hs[ll][j];
        int d = d0 + dd, l = l0 + ll;
        float delta = MIN_DECAY + (MAX_DECAY - MIN_DECAY) * (float)d * (1.0f / (DD - 1));
        float decay = expf(-((float)l * (1.0f / (LL - 1))) * fabsf(delta));
        g_k[(size_t)d * LL + l] = acc * decay;
    }
}

// ================= FFT passes (padded split re/im, fused radix-2 pairs) =================
__device__ __forceinline__ void dif_pass(float* xr, float* xi,
                                         const float* twr, const float* twi, int sh)
{
    const int tid = threadIdx.x;
    const int Hh = 1 << sh;
    for (int t = tid; t < 2048; t += 512) {
        int j = t & (Hh - 1);
        int g = t >> sh;
        int i0 = (g << (sh + 2)) + j;
        int p0 = PD(i0), p1 = PD(i0 + Hh), p2 = PD(i0 + 2 * Hh), p3 = PD(i0 + 3 * Hh);
        float x0r = xr[p0], x0i = xi[p0], x1r = xr[p1], x1i = xi[p1];
        float x2r = xr[p2], x2i = xi[p2], x3r = xr[p3], x3i = xi[p3];
        int ti = PD(j << (11 - sh));
        float wr = twr[ti], wi = twi[ti];
        float u0r = x0r + x2r, u0i = x0i + x2i;
        float d0r = x0r - x2r, d0i = x0i - x2i;
        float u2r = d0r * wr - d0i * wi, u2i = d0r * wi + d0i * wr;
        float u1r = x1r + x3r, u1i = x1i + x3i;
        float d1r = x1r - x3r, d1i = x1i - x3i;
        float u3r = d1r * wi + d1i * wr;          // * (wi - i*wr)
        float u3i = d1i * wi - d1r * wr;
        float br = wr * wr - wi * wi, bi = 2.f * wr * wi;   // w^2
        xr[p0] = u0r + u1r; xi[p0] = u0i + u1i;
        float e0r = u0r - u1r, e0i = u0i - u1i;
        xr[p1] = e0r * br - e0i * bi; xi[p1] = e0r * bi + e0i * br;
        xr[p2] = u2r + u3r; xi[p2] = u2i + u3i;
        float e1r = u2r - u3r, e1i = u2i - u3i;
        xr[p3] = e1r * br - e1i * bi; xi[p3] = e1r * bi + e1i * br;
    }
}

__device__ __forceinline__ void dit_pass(float* xr, float* xi,
                                         const float* twr, const float* twi, int sh)
{
    const int tid = threadIdx.x;
    const int h = 1 << sh;
    for (int t = tid; t < 2048; t += 512) {
        int j = t & (h - 1);
        int g = t >> sh;
        int i0 = (g << (sh + 2)) + j;
        int p0 = PD(i0), p1 = PD(i0 + h), p2 = PD(i0 + 2 * h), p3 = PD(i0 + 3 * h);
        float x0r = xr[p0], x0i = xi[p0], x1r = xr[p1], x1i = xi[p1];
        float x2r = xr[p2], x2i = xi[p2], x3r = xr[p3], x3i = xi[p3];
        int ti = PD(j << (11 - sh));
        float ar = twr[ti], ai = -twi[ti];            // V2 = conj(tw)
        float vr = ar * ar - ai * ai, vi = 2.f * ar * ai;   // V = V2^2
        float m1r = x1r * vr - x1i * vi, m1i = x1r * vi + x1i * vr;
        float t0r = x0r + m1r, t0i = x0i + m1i;
        float t1r = x0r - m1r, t1i = x0i - m1i;
        float m3r = x3r * vr - x3i * vi, m3i = x3r * vi + x3i * vr;
        float t2r = x2r + m3r, t2i = x2i + m3i;
        float t3r = x2r - m3r, t3i = x2i - m3i;
        float q2r = t2r * ar - t2i * ai, q2i = t2r * ai + t2i * ar;
        xr[p0] = t0r + q2r; xi[p0] = t0i + q2i;
        xr[p2] = t0r - q2r; xi[p2] = t0i - q2i;
        float q3r = -t3r * ai - t3i * ar;             // t3 * (i*V2)
        float q3i =  t3r * ar - t3i * ai;
        xr[p1] = t1r + q3r; xi[p1] = t1i + q3i;
        xr[p3] = t1r - q3r; xi[p3] = t1i - q3i;
    }
}

// ---------------- FFT of filter rows -> full spectra (DIF order) ----------------
__global__ __launch_bounds__(512, 2) void k_fft_k()
{
    extern __shared__ float fsm[];
    float* xr  = fsm;
    float* xi  = xr + XPAD;
    float* twr = xi + XPAD;
    float* twi = twr + TPAD;
    const int d = blockIdx.x;
    const int tid = threadIdx.x;

    for (int j = tid; j < 2048; j += 512) {
        float2 w = g_tw2[j];
        int p = PD(j);
        twr[p] = w.x; twi[p] = w.y;
    }
    const float* kr = g_k + (size_t)d * LL;
    for (int l = tid; l < LL; l += 512) { int p = PD(l); xr[p] = kr[l]; xi[p] = 0.f; }
    for (int l = LL + tid; l < NFFT; l += 512) { int p = PD(l); xr[p] = 0.f; xi[p] = 0.f; }
    __syncthreads();

    for (int sh = 11; sh >= 1; sh -= 2) { dif_pass(xr, xi, twr, twi, sh); __syncthreads(); }

    // final half=1 DIF stage + store
    float2* kf = g_kf + (size_t)d * NFFT;
    for (int t = tid; t < 4096; t += 512) {
        int p0 = PD(2 * t), p1 = PD(2 * t + 1);
        float a_r = xr[p0], a_i = xi[p0], b_r = xr[p1], b_i = xi[p1];
        kf[2 * t]     = make_float2(a_r + b_r, a_i + b_i);
        kf[2 * t + 1] = make_float2(a_r - b_r, a_i - b_i);
    }
}

// ---------------- fused: short conv + gate + FFT conv + gate + bf16 split ----------------
__device__ __forceinline__ float sconv3(const float* __restrict__ u, int l,
                                        float wa, float wb, float wc, float bs)
{
    float acc = bs + wc * u[l];
    if (l >= 1) acc += wb * u[l - 1];
    if (l >= 2) acc += wa * u[l - 2];
    return acc;
}

__global__ __launch_bounds__(512, 2)
void k_fftconv(const float* __restrict__ sw, const float* __restrict__ sb,
               const float* __restrict__ fbias)
{
    extern __shared__ float fsm[];
    float* xr  = fsm;
    float* xi  = xr + XPAD;
    float* twr = xi + XPAD;
    float* twi = twr + TPAD;
    const int d = blockIdx.x;
    const int tid = threadIdx.x;

    for (int j = tid; j < 2048; j += 512) {
        float2 w = g_tw2[j];
        int p = PD(j);
        twr[p] = w.x; twi[p] = w.y;
    }

    // rows of g_u: (b*N3 + part*DD + d)
    const float* u01 = g_u + ((size_t)(0 * N3 + DD) + d) * LL;
    const float* u02 = g_u + ((size_t)(0 * N3 + 2 * DD) + d) * LL;
    const float* u11 = g_u + ((size_t)(1 * N3 + DD) + d) * LL;
    const float* u12 = g_u + ((size_t)(1 * N3 + 2 * DD) + d) * LL;

    {
        float w1a = sw[(DD + d) * 3 + 0], w1b = sw[(DD + d) * 3 + 1], w1c = sw[(DD + d) * 3 + 2];
        float w2a = sw[(2 * DD + d) * 3 + 0], w2b = sw[(2 * DD + d) * 3 + 1], w2c = sw[(2 * DD + d) * 3 + 2];
        float b1c = sb[DD + d], b2c = sb[2 * DD + d];
        for (int l = tid; l < LL; l += 512) {
            float v0 = sconv3(u02, l, w2a, w2b, w2c, b2c) * sconv3(u01, l, w1a, w1b, w1c, b1c);
            float v1 = sconv3(u12, l, w2a, w2b, w2c, b2c) * sconv3(u11, l, w1a, w1b, w1c, b1c);
            int p = PD(l);
            xr[p] = v0; xi[p] = v1;
        }
        for (int l = LL + tid; l < NFFT; l += 512) { int p = PD(l); xr[p] = 0.f; xi[p] = 0.f; }
    }
    __syncthreads();

    for (int sh = 11; sh >= 1; sh -= 2) { dif_pass(xr, xi, twr, twi, sh); __syncthreads(); }

    // middle: DIF h=1 + K multiply + DIT h=1 (all in bit-reversed bin order)
    {
        const float2* kf = g_kf + (size_t)d * NFFT;
        for (int t = tid; t < 4096; t += 512) {
            int p0 = PD(2 * t), p1 = PD(2 * t + 1);
            float a_r = xr[p0], a_i = xi[p0], b_r = xr[p1], b_i = xi[p1];
            float er = a_r + b_r, ei = a_i + b_i;
            float orr = a_r - b_r, oi = a_i - b_i;
            float2 K0 = kf[2 * t], K1 = kf[2 * t + 1];
            float Er = er * K0.x - ei * K0.y,  Ei = er * K0.y + ei * K0.x;
            float Or = orr * K1.x - oi * K1.y, Oi = orr * K1.y + oi * K1.x;
            xr[p0] = Er + Or; xi[p0] = Ei + Oi;
            xr[p1] = Er - Or; xi[p1] = Ei - Oi;
        }
    }
    __syncthreads();

    for (int sh = 1; sh <= 11; sh += 2) { dit_pass(xr, xi, twr, twi, sh); __syncthreads(); }

    // epilogue: recompute x0, v; gate; split bf16; store (b,d,l)
    {
        const float* u00 = g_u + ((size_t)(0 * N3) + d) * LL;
        const float* u10 = g_u + ((size_t)(1 * N3) + d) * LL;
        float w0a = sw[d * 3 + 0], w0b = sw[d * 3 + 1], w0c = sw[d * 3 + 2];
        float w1a = sw[(DD + d) * 3 + 0], w1b = sw[(DD + d) * 3 + 1], w1c = sw[(DD + d) * 3 + 2];
        float w2a = sw[(2 * DD + d) * 3 + 0], w2b = sw[(2 * DD + d) * 3 + 1], w2c = sw[(2 * DD + d) * 3 + 2];
        float b0c = sb[d], b1c = sb[DD + d], b2c = sb[2 * DD + d];
        const float bi = fbias[d];
        const float inv = 1.0f / (float)NFFT;
        __nv_bfloat16* gh0 = g_gh + (size_t)d * LL;
        __nv_bfloat16* gl0 = g_gl + (size_t)d * LL;
        __nv_bfloat16* gh1 = g_gh + ((size_t)DD + d) * LL;
        __nv_bfloat16* gl1 = g_gl + ((size_t)DD + d) * LL;
        for (int l = tid; l < LL; l += 512) {
            int p = PD(l);
            float x0_0 = sconv3(u00, l, w0a, w0b, w0c, b0c);
            float v_0  = sconv3(u02, l, w2a, w2b, w2c, b2c) * sconv3(u01, l, w1a, w1b, w1c, b1c);
            float x0_1 = sconv3(u10, l, w0a, w0b, w0c, b0c);
            float v_1  = sconv3(u12, l, w2a, w2b, w2c, b2c) * sconv3(u11, l, w1a, w1b, w1c, b1c);
            float r0 = (xr[p] * inv + v_0 * bi) * x0_0;
            float r1 = (xi[p] * inv + v_1 * bi) * x0_1;
            __nv_bfloat16 h0 = __float2bfloat16(r0);
            __nv_bfloat16 h1 = __float2bfloat16(r1);
            gh0[l] = h0; gl0[l] = __float2bfloat16(r0 - __bfloat162float(h0));
            gh1[l] = h1; gl1[l] = __float2bfloat16(r1 - __bfloat162float(h1));
        }
    }
}

// ---------------- launch ----------------
extern "C" void kernel_launch(void* const* d_in, const int* in_sizes, int n_in,
                              void* d_out, int out_size)
{
    const float* x    = (const float*)d_in[0];
    const float* iw   = (const float*)d_in[1];
    const float* ib   = (const float*)d_in[2];
    const float* sw   = (const float*)d_in[3];
    const float* sb   = (const float*)d_in[4];
    const float* w0   = (const float*)d_in[5];
    const float* b0   = (const float*)d_in[6];
    const float* fr   = (const float*)d_in[7];
    const float* w1   = (const float*)d_in[8];
    const float* b1   = (const float*)d_in[9];
    const float* w2   = (const float*)d_in[10];
    const float* b2   = (const float*)d_in[11];
    const float* w3   = (const float*)d_in[12];
    const float* fb   = (const float*)d_in[13];
    const float* ow   = (const float*)d_in[14];
    const float* ob   = (const float*)d_in[15];
    float* out = (float*)d_out;

    (void)cudaFuncSetAttribute(k_fft_k,    cudaFuncAttributeMaxDynamicSharedMemorySize, FFT_SMEM);
    (void)cudaFuncSetAttribute(k_fftconv,  cudaFuncAttributeMaxDynamicSharedMemorySize, FFT_SMEM);
    (void)cudaFuncSetAttribute(k_gemm_in,  cudaFuncAttributeMaxDynamicSharedMemorySize, GEMM_SMEM);
    (void)cudaFuncSetAttribute(k_gemm_out, cudaFuncAttributeMaxDynamicSharedMemorySize, GEMM_SMEM);

    __nv_bfloat16 *xh, *xl, *wih, *wil, *gh, *gl, *woh, *wol;
    cudaGetSymbolAddress((void**)&xh,  g_xh);  cudaGetSymbolAddress((void**)&xl,  g_xl);
    cudaGetSymbolAddress((void**)&wih, g_wih); cudaGetSymbolAddress((void**)&wil, g_wil);
    cudaGetSymbolAddress((void**)&gh,  g_gh);  cudaGetSymbolAddress((void**)&gl,  g_gl);
    cudaGetSymbolAddress((void**)&woh, g_woh); cudaGetSymbolAddress((void**)&wol, g_wol);

    int n4;
    n4 = (MROWS * KDIM) / 4;  k_split<<<(n4 + 255) / 256, 256>>>(x,  xh,  xl,  n4);   // 1
    n4 = (N3 * KDIM) / 4;     k_split<<<(n4 + 255) / 256, 256>>>(iw, wih, wil, n4);   // 2
    n4 = (DD * KDIM) / 4;     k_split<<<(n4 + 255) / 256, 256>>>(ow, woh, wol, n4);   // 3
    k_twiddle<<<4, 512>>>();                                                          // 4
    k_filter_h<<<LL / 4, 256>>>(w0, b0, fr, w1, b1, w2, b2);                          // 5
    k_gemm_in<<<dim3(N3 / 128, MROWS / 128), 256, GEMM_SMEM>>>(xh, xl, wih, wil, ib); // 6 (profiled)
    k_filter_k<<<dim3(LL / 64, DD / 64), 256>>>(w3);                                  // 7
    k_fft_k<<<DD, 512, FFT_SMEM>>>();                                                 // 8
    k_fftconv<<<DD, 512, FFT_SMEM>>>(sw, sb, fb);                                     // 9
    k_gemm_out<<<dim3(2048 / 128, MROWS / 128), 256, GEMM_SMEM>>>(gh, gl, woh, wol, ob, out); // 10
}

// round 7
// speedup vs baseline: 5.0647x; 1.0474x over previous
#include <cuda_runtime.h>
#include <cuda_bf16.h>
#include <cuda_fp16.h>
#include <cstdint>

// ---------------- problem constants ----------------
#define BB      2
#define DD      2048
#define LL      4096
#define N3      6144          // 3*D
#define NFFT    8192          // 2*L
#define ORD     64            // filter order
#define KDIM    2048          // GEMM K (both GEMMs)
#define MROWS   8192          // GEMM M (B*L)

// GEMM tiling
#define Bb_K 32
#define NCHUNK (KDIM / Bb_K)          // 64
#define MAT_BYTES  (128 * 32 * 2)     // 8192 per matrix per stage
#define STAGE_BYTES (4 * MAT_BYTES)   // 32768
#define GEMM_SMEM  (4 * STAGE_BYTES)  // 131072 (4-stage)

// FFT smem layout (floats), padded idx = i + (i>>5)
#define PD(i) ((i) + ((i) >> 5))
#define XPAD 8448
#define TPAD 2112
#define FFT_SMEM ((2 * XPAD + 2 * TPAD) * 4)   // 84480 bytes

// ---------------- scratch (device globals) ----------------
__device__ float  g_u [(size_t)BB * N3 * LL];     // in_proj output, (b, c, l)
__device__ float  g_k [(size_t)DD * LL];          // filter k, (d, l)
__device__ float  g_h [(size_t)LL * ORD];         // MLP features h, (l, o)
__device__ __half2 g_kf[(size_t)DD * NFFT];       // K full spectra (DIF order, fp16)
__device__ float2 g_tw2[2048];                    // twiddles e^{-2pi i m/8192}, m<2048

// bf16 split operands
__device__ __nv_bfloat16 g_xh [(size_t)MROWS * KDIM];
__device__ __nv_bfloat16 g_xl [(size_t)MROWS * KDIM];
__device__ __nv_bfloat16 g_wih[(size_t)N3 * KDIM];
__device__ __nv_bfloat16 g_wil[(size_t)N3 * KDIM];
__device__ __nv_bfloat16 g_gh [(size_t)BB * DD * LL];   // gated output, (b,d,l)
__device__ __nv_bfloat16 g_gl [(size_t)BB * DD * LL];
__device__ __nv_bfloat16 g_woh[(size_t)DD * KDIM];
__device__ __nv_bfloat16 g_wol[(size_t)DD * KDIM];

// ---------------- PTX helpers ----------------
__device__ __forceinline__ uint32_t smem_u32(const void* p) {
    uint32_t a;
    asm("{ .reg .u64 t; cvta.to.shared.u64 t, %1; cvt.u32.u64 %0, t; }" : "=r"(a) : "l"(p));
    return a;
}
__device__ __forceinline__ void cpa16(uint32_t dst, const void* src) {
    asm volatile("cp.async.cg.shared.global [%0], [%1], 16;" :: "r"(dst), "l"(src) : "memory");
}
#define CPA_COMMIT() asm volatile("cp.async.commit_group;" ::: "memory")
#define CPA_WAIT2()  asm volatile("cp.async.wait_group 2;" ::: "memory")
#define CPA_WAIT1()  asm volatile("cp.async.wait_group 1;" ::: "memory")
#define CPA_WAIT0()  asm volatile("cp.async.wait_group 0;" ::: "memory")

#define LDX4(r, addr) \
    asm volatile("ldmatrix.sync.aligned.m8n8.x4.shared.b16 {%0,%1,%2,%3}, [%4];" \
        : "=r"((r)[0]), "=r"((r)[1]), "=r"((r)[2]), "=r"((r)[3]) : "r"(addr))
#define LDX4T(r, addr) \
    asm volatile("ldmatrix.sync.aligned.m8n8.x4.trans.shared.b16 {%0,%1,%2,%3}, [%4];" \
        : "=r"((r)[0]), "=r"((r)[1]), "=r"((r)[2]), "=r"((r)[3]) : "r"(addr))

#define MMA16816(d, a, b0, b1) \
    asm volatile("mma.sync.aligned.m16n8k16.row.col.f32.bf16.bf16.f32 " \
        "{%0,%1,%2,%3}, {%4,%5,%6,%7}, {%8,%9}, {%0,%1,%2,%3};" \
        : "+f"((d)[0]), "+f"((d)[1]), "+f"((d)[2]), "+f"((d)[3]) \
        : "r"((a)[0]), "r"((a)[1]), "r"((a)[2]), "r"((a)[3]), "r"(b0), "r"(b1))

__device__ __forceinline__ uint32_t swz(uint32_t off) {
    return off ^ ((off >> 3) & 0x30u);
}
__device__ __forceinline__ int brev13(int x) {
    return (int)(__brev((unsigned)x) >> 19);
}

// ---------------- twiddle table ----------------
__global__ void k_twiddle() {
    int j = blockIdx.x * blockDim.x + threadIdx.x;
    if (j < 2048) {
        double a = -2.0 * 3.14159265358979323846 * (double)j / (double)NFFT;
        g_tw2[j] = make_float2((float)cos(a), (float)sin(a));
    }
}

// ---------------- fp32 -> bf16 hi/lo split ----------------
__global__ void k_split(const float* __restrict__ in, __nv_bfloat16* __restrict__ hi,
                        __nv_bfloat16* __restrict__ lo, int n4)
{
    int i = blockIdx.x * blockDim.x + threadIdx.x;
    if (i >= n4) return;
    float4 v = ((const float4*)in)[i];
    __nv_bfloat16 h0 = __float2bfloat16(v.x), h1 = __float2bfloat16(v.y);
    __nv_bfloat16 h2 = __float2bfloat16(v.z), h3 = __float2bfloat16(v.w);
    __nv_bfloat162 hh0 = {h0, h1}, hh1 = {h2, h3};
    ((__nv_bfloat162*)hi)[i * 2 + 0] = hh0;
    ((__nv_bfloat162*)hi)[i * 2 + 1] = hh1;
    __nv_bfloat162 ll0 = {__float2bfloat16(v.x - __bfloat162float(h0)),
                          __float2bfloat16(v.y - __bfloat162float(h1))};
    __nv_bfloat162 ll1 = {__float2bfloat16(v.z - __bfloat162float(h2)),
                          __float2bfloat16(v.w - __bfloat162float(h3))};
    ((__nv_bfloat162*)lo)[i * 2 + 0] = ll0;
    ((__nv_bfloat162*)lo)[i * 2 + 1] = ll1;
}

// ================= GEMM 1: in_proj (A row-major (m,k)), 4-stage 1-sync =================
__global__ __launch_bounds__(256, 1)
void k_gemm_in(const __nv_bfloat16* __restrict__ Ah, const __nv_bfloat16* __restrict__ Al,
               const __nv_bfloat16* __restrict__ Bh, const __nv_bfloat16* __restrict__ Bl,
               const float* __restrict__ bias)
{
    extern __shared__ __align__(128) unsigned char dsm[];
    const uint32_t sb = smem_u32(dsm);
    const int tid  = threadIdx.x;
    const int lane = tid & 31;
    const int wid  = tid >> 5;
    const int wm   = wid >> 2;
    const int wn   = wid & 3;
    const int m0 = blockIdx.y * 128;
    const int n0 = blockIdx.x * 128;

    int row0 = tid >> 2, c0 = tid & 3;
    int row1 = (tid + 256) >> 2, c1 = (tid + 256) & 3;
    uint32_t so0 = swz((uint32_t)(row0 * 64 + c0 * 16));
    uint32_t so1 = swz((uint32_t)(row1 * 64 + c1 * 16));
    const __nv_bfloat16* pAh = Ah + (size_t)(m0 + row0) * KDIM + c0 * 8;
    const __nv_bfloat16* pAl = Al + (size_t)(m0 + row0) * KDIM + c0 * 8;
    const __nv_bfloat16* pBh = Bh + (size_t)(n0 + row0) * KDIM + c0 * 8;
    const __nv_bfloat16* pBl = Bl + (size_t)(n0 + row0) * KDIM + c0 * 8;
    const __nv_bfloat16* qAh = Ah + (size_t)(m0 + row1) * KDIM + c1 * 8;
    const __nv_bfloat16* qAl = Al + (size_t)(m0 + row1) * KDIM + c1 * 8;
    const __nv_bfloat16* qBh = Bh + (size_t)(n0 + row1) * KDIM + c1 * 8;
    const __nv_bfloat16* qBl = Bl + (size_t)(n0 + row1) * KDIM + c1 * 8;

#define LOADST(st, k0) do {                                                  \
        uint32_t base = sb + (uint32_t)(st) * STAGE_BYTES;                   \
        cpa16(base + so0,                 pAh + (k0));                       \
        cpa16(base + so1,                 qAh + (k0));                       \
        cpa16(base + MAT_BYTES + so0,     pAl + (k0));                       \
        cpa16(base + MAT_BYTES + so1,     qAl + (k0));                       \
        cpa16(base + 2 * MAT_BYTES + so0, pBh + (k0));                       \
        cpa16(base + 2 * MAT_BYTES + so1, qBh + (k0));                       \
        cpa16(base + 3 * MAT_BYTES + so0, pBl + (k0));                       \
        cpa16(base + 3 * MAT_BYTES + so1, qBl + (k0));                       \
        CPA_COMMIT();                                                        \
    } while (0)

    uint32_t aoffs[4][2], boffs[4];
    {
        int ra = lane & 15, ka = (lane >> 4) * 16;
        int rb = lane & 7,  kb = (lane >> 3) * 16;
#pragma unroll
        for (int mi = 0; mi < 4; mi++)
#pragma unroll
            for (int s = 0; s < 2; s++)
                aoffs[mi][s] = swz((uint32_t)((wm * 64 + mi * 16 + ra) * 64 + s * 32 + ka));
#pragma unroll
        for (int ni = 0; ni < 4; ni++)
            boffs[ni] = swz((uint32_t)((wn * 32 + ni * 8 + rb) * 64 + kb));
    }

    float acc[4][4][4];
#pragma unroll
    for (int mi = 0; mi < 4; mi++)
#pragma unroll
        for (int ni = 0; ni < 4; ni++)
#pragma unroll
            for (int r = 0; r < 4; r++) acc[mi][ni][r] = 0.f;

    LOADST(0, 0);
    LOADST(1, 1 * Bb_K);
    LOADST(2, 2 * Bb_K);

    for (int i = 0; i < NCHUNK; i++) {
        if (i + 2 < NCHUNK)      { CPA_WAIT2(); }
        else if (i + 1 < NCHUNK) { CPA_WAIT1(); }
        else                     { CPA_WAIT0(); }
        __syncthreads();
        if (i + 3 < NCHUNK) LOADST((i + 3) & 3, (i + 3) * Bb_K);

        uint32_t base = sb + (uint32_t)(i & 3) * STAGE_BYTES;
        uint32_t bh[4][4], bl[4][4];
#pragma unroll
        for (int ni = 0; ni < 4; ni++) {
            LDX4(bh[ni], base + 2 * MAT_BYTES + boffs[ni]);
            LDX4(bl[ni], base + 3 * MAT_BYTES + boffs[ni]);
        }
#pragma unroll
        for (int s = 0; s < 2; s++) {
            uint32_t ah[4][4], al[4][4];
#pragma unroll
            for (int mi = 0; mi < 4; mi++) {
                LDX4(ah[mi], base + aoffs[mi][s]);
                LDX4(al[mi], base + MAT_BYTES + aoffs[mi][s]);
            }
#pragma unroll
            for (int mi = 0; mi < 4; mi++)
#pragma unroll
                for (int ni = 0; ni < 4; ni++) {
                    MMA16816(acc[mi][ni], ah[mi], bh[ni][2 * s], bh[ni][2 * s + 1]);
                    MMA16816(acc[mi][ni], ah[mi], bl[ni][2 * s], bl[ni][2 * s + 1]);
                    MMA16816(acc[mi][ni], al[mi], bh[ni][2 * s], bh[ni][2 * s + 1]);
                }
        }
    }
#undef LOADST
    __syncthreads();

    // epilogue: transpose via smem, store (b,c,l)
    float* ep = (float*)dsm;
    const int r  = lane >> 2;
    const int cc = 2 * (lane & 3);
#pragma unroll
    for (int mi = 0; mi < 4; mi++)
#pragma unroll
        for (int ni = 0; ni < 4; ni++) {
            int mloc = wm * 64 + mi * 16 + r;
            int nloc = wn * 32 + ni * 8 + cc;
            const float* a = acc[mi][ni];
            ep[nloc * 132 + mloc]           = a[0];
            ep[(nloc + 1) * 132 + mloc]     = a[1];
            ep[nloc * 132 + mloc + 8]       = a[2];
            ep[(nloc + 1) * 132 + mloc + 8] = a[3];
        }
    __syncthreads();

    const int erow = tid >> 1;
    const int half = tid & 1;
    const float* src = ep + erow * 132 + half * 64;
    const int b  = m0 >> 12;
    const int l0 = (m0 & (LL - 1)) + half * 64;
    const float bi = bias[n0 + erow];
    float* dst = g_u + ((size_t)b * N3 + n0 + erow) * LL + l0;
#pragma unroll
    for (int j = 0; j < 16; j++) {
        float4 v = *(const float4*)(src + j * 4);
        v.x += bi; v.y += bi; v.z += bi; v.w += bi;
        *(float4*)(dst + j * 4) = v;
    }
}

// ================= GEMM 2: out_proj (A from (b,d,l) via ldmatrix.trans), 4-stage =================
__global__ __launch_bounds__(256, 1)
void k_gemm_out(const __nv_bfloat16* __restrict__ Ah, const __nv_bfloat16* __restrict__ Al,
                const __nv_bfloat16* __restrict__ Bh, const __nv_bfloat16* __restrict__ Bl,
                const float* __restrict__ bias, float* __restrict__ Out)
{
    extern __shared__ __align__(128) unsigned char dsm[];
    const uint32_t sb = smem_u32(dsm);
    const int tid  = threadIdx.x;
    const int lane = tid & 31;
    const int wid  = tid >> 5;
    const int wm   = wid >> 2;
    const int wn   = wid & 3;
    const int m0 = blockIdx.y * 128;
    const int n0 = blockIdx.x * 128;
    const int bb = m0 >> 12;
    const int l0 = m0 & (LL - 1);

    int rA = tid >> 4, cA = tid & 15;
    uint32_t soA0 = (uint32_t)(rA * 256 + ((cA ^ (rA & 7)) << 4));
    uint32_t soA1 = soA0 + 4096;
    const __nv_bfloat16* pAh0 = Ah + ((size_t)bb * DD + rA) * LL + l0 + cA * 8;
    const __nv_bfloat16* pAl0 = Al + ((size_t)bb * DD + rA) * LL + l0 + cA * 8;
    const __nv_bfloat16* pAh1 = pAh0 + (size_t)16 * LL;
    const __nv_bfloat16* pAl1 = pAl0 + (size_t)16 * LL;

    int rowB0 = tid >> 2, cB0 = tid & 3;
    int rowB1 = (tid + 256) >> 2, cB1 = (tid + 256) & 3;
    uint32_t soB0 = swz((uint32_t)(rowB0 * 64 + cB0 * 16));
    uint32_t soB1 = swz((uint32_t)(rowB1 * 64 + cB1 * 16));
    const __nv_bfloat16* pBh = Bh + (size_t)(n0 + rowB0) * KDIM + cB0 * 8;
    const __nv_bfloat16* pBl = Bl + (size_t)(n0 + rowB0) * KDIM + cB0 * 8;
    const __nv_bfloat16* qBh = Bh + (size_t)(n0 + rowB1) * KDIM + cB1 * 8;
    const __nv_bfloat16* qBl = Bl + (size_t)(n0 + rowB1) * KDIM + cB1 * 8;

#define LOADST2(st, ci) do {                                                   \
        uint32_t base = sb + (uint32_t)(st) * STAGE_BYTES;                     \
        size_t ko = (size_t)(ci) * Bb_K * LL;                                  \
        int kb = (ci) * Bb_K;                                                  \
        cpa16(base + soA0,                 pAh0 + ko);                         \
        cpa16(base + soA1,                 pAh1 + ko);                         \
        cpa16(base + MAT_BYTES + soA0,     pAl0 + ko);                         \
        cpa16(base + MAT_BYTES + soA1,     pAl1 + ko);                         \
        cpa16(base + 2 * MAT_BYTES + soB0, pBh + kb);                          \
        cpa16(base + 2 * MAT_BYTES + soB1, qBh + kb);                          \
        cpa16(base + 3 * MAT_BYTES + soB0, pBl + kb);                          \
        cpa16(base + 3 * MAT_BYTES + soB1, qBl + kb);                          \
        CPA_COMMIT();                                                          \
    } while (0)

    uint32_t aoffT[4][2], boffs[4];
    {
        int kr = (lane & 7) + ((lane >> 4) << 3);
        int msub = ((lane >> 3) & 1) * 8;
        int rb = lane & 7, kb = (lane >> 3) * 16;
#pragma unroll
        for (int mi = 0; mi < 4; mi++)
#pragma unroll
            for (int s = 0; s < 2; s++) {
                int row = s * 16 + kr;
                int mcChunk = (wm * 64 + mi * 16 + msub) >> 3;
                aoffT[mi][s] = (uint32_t)(row * 256 + ((mcChunk ^ (row & 7)) << 4));
            }
#pragma unroll
        for (int ni = 0; ni < 4; ni++)
            boffs[ni] = swz((uint32_t)((wn * 32 + ni * 8 + rb) * 64 + kb));
    }

    float acc[4][4][4];
#pragma unroll
    for (int mi = 0; mi < 4; mi++)
#pragma unroll
        for (int ni = 0; ni < 4; ni++)
#pragma unroll
            for (int r = 0; r < 4; r++) acc[mi][ni][r] = 0.f;

    LOADST2(0, 0);
    LOADST2(1, 1);
    LOADST2(2, 2);

    for (int i = 0; i < NCHUNK; i++) {
        if (i + 2 < NCHUNK)      { CPA_WAIT2(); }
        else if (i + 1 < NCHUNK) { CPA_WAIT1(); }
        else                     { CPA_WAIT0(); }
        __syncthreads();
        if (i + 3 < NCHUNK) LOADST2((i + 3) & 3, i + 3);

        uint32_t base = sb + (uint32_t)(i & 3) * STAGE_BYTES;
        uint32_t bh[4][4], bl[4][4];
#pragma unroll
        for (int ni = 0; ni < 4; ni++) {
            LDX4(bh[ni], base + 2 * MAT_BYTES + boffs[ni]);
            LDX4(bl[ni], base + 3 * MAT_BYTES + boffs[ni]);
        }
#pragma unroll
        for (int s = 0; s < 2; s++) {
            uint32_t ah[4][4], al[4][4];
#pragma unroll
            for (int mi = 0; mi < 4; mi++) {
                LDX4T(ah[mi], base + aoffT[mi][s]);
                LDX4T(al[mi], base + MAT_BYTES + aoffT[mi][s]);
            }
#pragma unroll
            for (int mi = 0; mi < 4; mi++)
#pragma unroll
                for (int ni = 0; ni < 4; ni++) {
                    MMA16816(acc[mi][ni], ah[mi], bh[ni][2 * s], bh[ni][2 * s + 1]);
                    MMA16816(acc[mi][ni], ah[mi], bl[ni][2 * s], bl[ni][2 * s + 1]);
                    MMA16816(acc[mi][ni], al[mi], bh[ni][2 * s], bh[ni][2 * s + 1]);
                }
        }
    }
#undef LOADST2
    __syncthreads();

    float* ep = (float*)dsm;
    const int r  = lane >> 2;
    const int cc = 2 * (lane & 3);
#pragma unroll
    for (int mi = 0; mi < 4; mi++)
#pragma unroll
        for (int ni = 0; ni < 4; ni++) {
            int mloc = wm * 64 + mi * 16 + r;
            int nloc = wn * 32 + ni * 8 + cc;
            const float* a = acc[mi][ni];
            ep[mloc * 132 + nloc]           = a[0];
            ep[mloc * 132 + nloc + 1]       = a[1];
            ep[(mloc + 8) * 132 + nloc]     = a[2];
            ep[(mloc + 8) * 132 + nloc + 1] = a[3];
        }
    __syncthreads();

    const int erow = tid >> 1;
    const int half = tid & 1;
    const float* src = ep + erow * 132 + half * 64;
    float* dst = Out + (size_t)(m0 + erow) * 2048 + n0 + half * 64;
    const float* bp = bias + n0 + half * 64;
#pragma unroll
    for (int j = 0; j < 16; j++) {
        float4 v = *(const float4*)(src + j * 4);
        float4 bv = *(const float4*)(bp + j * 4);
        v.x += bv.x; v.y += bv.y; v.z += bv.z; v.w += bv.w;
        *(float4*)(dst + j * 4) = v;
    }
}

// ---------------- filter MLP features h(l) ----------------
__global__ __launch_bounds__(256)
void k_filter_h(const float* __restrict__ w0, const float* __restrict__ b0,
                const float* __restrict__ fr,
                const float* __restrict__ w1, const float* __restrict__ b1,
                const float* __restrict__ w2, const float* __restrict__ b2)
{
    __shared__ float hb[2][4][ORD];
    int o  = threadIdx.x & 63;
    int sl = threadIdx.x >> 6;
    int l  = blockIdx.x * 4 + sl;

    float t    = (float)l * (1.0f / (LL - 1));
    float wang = 6.28318530717958647692f * (float)l * (1.0f / LL);
    float ang  = 1e-4f * wang;
    float z0 = t, z1 = cosf(ang), z2 = -sinf(ang);
    float f = fr[o];

    float h = sinf(f * (w0[o * 3 + 0] * z0 + w0[o * 3 + 1] * z1 + w0[o * 3 + 2] * z2 + b0[o]));
    hb[0][sl][o] = h;
    __syncthreads();

    float acc = b1[o];
#pragma unroll
    for (int j = 0; j < ORD; j++) acc += w1[o * ORD + j] * hb[0][sl][j];
    h = sinf(f * acc);
    hb[1][sl][o] = h;
    __syncthreads();

    acc = b2[o];
#pragma unroll
    for (int j = 0; j < ORD; j++) acc += w2[o * ORD + j] * hb[1][sl][j];
    h = sinf(f * acc);
    g_h[(size_t)l * ORD + o] = h;
}

// ---------------- filter k(d,l) ----------------
#define MIN_DECAY (-3.0701134573253937f)
#define MAX_DECAY (-15.350567286626969f)
__global__ __launch_bounds__(256)
void k_filter_k(const float* __restrict__ W3)
{
    __shared__ float hs[64][65];
    __shared__ float ws[64][64];
    int l0 = blockIdx.x * 64;
    int d0 = blockIdx.y * 64;
    for (int i = threadIdx.x; i < 64 * 64; i += 256) {
        int r = i >> 6, cidx = i & 63;
        hs[r][cidx] = g_h[(size_t)(l0 + r) * ORD + cidx];
        ws[r][cidx] = W3[(size_t)(d0 + r) * ORD + cidx];
    }
    __syncthreads();
    for (int i = threadIdx.x; i < 64 * 64; i += 256) {
        int ll = i & 63;
        int dd = i >> 6;
        float acc = 0.f;
#pragma unroll
        for (int j = 0; j < ORD; j++) acc += ws[dd][j] * hs[ll][j];
        int d = d0 + dd, l = l0 + ll;
        float delta = MIN_DECAY + (MAX_DECAY - MIN_DECAY) * (float)d * (1.0f / (DD - 1));
        float decay = expf(-((float)l * (1.0f / (LL - 1))) * fabsf(delta));
        g_k[(size_t)d * LL + l] = acc * decay;
    }
}

// ================= FFT passes (padded split re/im, fused radix-2 pairs) =================
__device__ __forceinline__ void dif_pass(float* xr, float* xi,
                                         const float* twr, const float* twi, int sh)
{
    const int tid = threadIdx.x;
    const int Hh = 1 << sh;
    for (int t = tid; t < 2048; t += 512) {
        int j = t & (Hh - 1);
        int g = t >> sh;
        int i0 = (g << (sh + 2)) + j;
        int p0 = PD(i0), p1 = PD(i0 + Hh), p2 = PD(i0 + 2 * Hh), p3 = PD(i0 + 3 * Hh);
        float x0r = xr[p0], x0i = xi[p0], x1r = xr[p1], x1i = xi[p1];
        float x2r = xr[p2], x2i = xi[p2], x3r = xr[p3], x3i = xi[p3];
        int ti = PD(j << (11 - sh));
        float wr = twr[ti], wi = twi[ti];
        float u0r = x0r + x2r, u0i = x0i + x2i;
        float d0r = x0r - x2r, d0i = x0i - x2i;
        float u2r = d0r * wr - d0i * wi, u2i = d0r * wi + d0i * wr;
        float u1r = x1r + x3r, u1i = x1i + x3i;
        float d1r = x1r - x3r, d1i = x1i - x3i;
        float u3r = d1r * wi + d1i * wr;
        float u3i = d1i * wi - d1r * wr;
        float br = wr * wr - wi * wi, bi = 2.f * wr * wi;
        xr[p0] = u0r + u1r; xi[p0] = u0i + u1i;
        float e0r = u0r - u1r, e0i = u0i - u1i;
        xr[p1] = e0r * br - e0i * bi; xi[p1] = e0r * bi + e0i * br;
        xr[p2] = u2r + u3r; xi[p2] = u2i + u3i;
        float e1r = u2r - u3r, e1i = u2i - u3i;
        xr[p3] = e1r * br - e1i * bi; xi[p3] = e1r * bi + e1i * br;
    }
}

__device__ __forceinline__ void dit_pass(float* xr, float* xi,
                                         const float* twr, const float* twi, int sh)
{
    const int tid = threadIdx.x;
    const int h = 1 << sh;
    for (int t = tid; t < 2048; t += 512) {
        int j = t & (h - 1);
        int g = t >> sh;
        int i0 = (g << (sh + 2)) + j;
        int p0 = PD(i0), p1 = PD(i0 + h), p2 = PD(i0 + 2 * h), p3 = PD(i0 + 3 * h);
        float x0r = xr[p0], x0i = xi[p0], x1r = xr[p1], x1i = xi[p1];
        float x2r = xr[p2], x2i = xi[p2], x3r = xr[p3], x3i = xi[p3];
        int ti = PD(j << (11 - sh));
        float ar = twr[ti], ai = -twi[ti];
        float vr = ar * ar - ai * ai, vi = 2.f * ar * ai;
        float m1r = x1r * vr - x1i * vi, m1i = x1r * vi + x1i * vr;
        float t0r = x0r + m1r, t0i = x0i + m1i;
        float t1r = x0r - m1r, t1i = x0i - m1i;
        float m3r = x3r * vr - x3i * vi, m3i = x3r * vi + x3i * vr;
        float t2r = x2r + m3r, t2i = x2i + m3i;
        float t3r = x2r - m3r, t3i = x2i - m3i;
        float q2r = t2r * ar - t2i * ai, q2i = t2r * ai + t2i * ar;
        xr[p0] = t0r + q2r; xi[p0] = t0i + q2i;
        xr[p2] = t0r - q2r; xi[p2] = t0i - q2i;
        float q3r = -t3r * ai - t3i * ar;
        float q3i =  t3r * ar - t3i * ai;
        xr[p1] = t1r + q3r; xi[p1] = t1i + q3i;
        xr[p3] = t1r - q3r; xi[p3] = t1i - q3i;
    }
}

// ---------------- FFT of filter rows: 2 rows packed per block -> fp16 spectra ----------------
__global__ __launch_bounds__(512, 2) void k_fft_k()
{
    extern __shared__ float fsm[];
    float* xr  = fsm;
    float* xi  = xr + XPAD;
    float* twr = xi + XPAD;
    float* twi = twr + TPAD;
    const int d  = blockIdx.x;          // 0..1023
    const int d2 = d + DD / 2;
    const int tid = threadIdx.x;

    for (int j = tid; j < 2048; j += 512) {
        float2 w = g_tw2[j];
        int p = PD(j);
        twr[p] = w.x; twi[p] = w.y;
    }
    const float* k0 = g_k + (size_t)d  * LL;
    const float* k1 = g_k + (size_t)d2 * LL;
    for (int l = tid; l < LL; l += 512) { int p = PD(l); xr[p] = k0[l]; xi[p] = k1[l]; }
    for (int l = LL + tid; l < NFFT; l += 512) { int p = PD(l); xr[p] = 0.f; xi[p] = 0.f; }
    __syncthreads();

    for (int sh = 11; sh >= 1; sh -= 2) { dif_pass(xr, xi, twr, twi, sh); __syncthreads(); }

    // final half=1 DIF stage, in place
    for (int t = tid; t < 4096; t += 512) {
        int p0 = PD(2 * t), p1 = PD(2 * t + 1);
        float a_r = xr[p0], a_i = xi[p0], b_r = xr[p1], b_i = xi[p1];
        xr[p0] = a_r + b_r; xi[p0] = a_i + b_i;
        xr[p1] = a_r - b_r; xi[p1] = a_i - b_i;
    }
    __syncthreads();

    // Hermitian unpack in bit-reversed position order -> fp16 spectra for d and d2
    __half2* kfa = g_kf + (size_t)d  * NFFT;
    __half2* kfb = g_kf + (size_t)d2 * NFFT;
    for (int p = tid; p < NFFT; p += 512) {
        int j  = brev13(p);
        int q  = brev13((NFFT - j) & (NFFT - 1));
        int pp = PD(p), pq = PD(q);
        float zpr = xr[pp], zpi = xi[pp];
        float zqr = xr[pq], zqi = xi[pq];
        float ar = 0.5f * (zpr + zqr), ai = 0.5f * (zpi - zqi);
        float br = 0.5f * (zpi + zqi), bi = 0.5f * (zqr - zpr);
        kfa[p] = __floats2half2_rn(ar, ai);
        kfb[p] = __floats2half2_rn(br, bi);
    }
}

// ---------------- fused: short conv + gate + FFT conv + gate + bf16 split ----------------
__device__ __forceinline__ float sconv3(const float* __restrict__ u, int l,
                                        float wa, float wb, float wc, float bs)
{
    float acc = bs + wc * u[l];
    if (l >= 1) acc += wb * u[l - 1];
    if (l >= 2) acc += wa * u[l - 2];
    return acc;
}

__global__ __launch_bounds__(512, 2)
void k_fftconv(const float* __restrict__ sw, const float* __restrict__ sb,
               const float* __restrict__ fbias)
{
    extern __shared__ float fsm[];
    float* xr  = fsm;
    float* xi  = xr + XPAD;
    float* twr = xi + XPAD;
    float* twi = twr + TPAD;
    const int d = blockIdx.x;
    const int tid = threadIdx.x;

    for (int j = tid; j < 2048; j += 512) {
        float2 w = g_tw2[j];
        int p = PD(j);
        twr[p] = w.x; twi[p] = w.y;
    }

    const float* u01 = g_u + ((size_t)(0 * N3 + DD) + d) * LL;
    const float* u02 = g_u + ((size_t)(0 * N3 + 2 * DD) + d) * LL;
    const float* u11 = g_u + ((size_t)(1 * N3 + DD) + d) * LL;
    const float* u12 = g_u + ((size_t)(1 * N3 + 2 * DD) + d) * LL;

    {
        float w1a = sw[(DD + d) * 3 + 0], w1b = sw[(DD + d) * 3 + 1], w1c = sw[(DD + d) * 3 + 2];
        float w2a = sw[(2 * DD + d) * 3 + 0], w2b = sw[(2 * DD + d) * 3 + 1], w2c = sw[(2 * DD + d) * 3 + 2];
        float b1c = sb[DD + d], b2c = sb[2 * DD + d];
        for (int l = tid; l < LL; l += 512) {
            float v0 = sconv3(u02, l, w2a, w2b, w2c, b2c) * sconv3(u01, l, w1a, w1b, w1c, b1c);
            float v1 = sconv3(u12, l, w2a, w2b, w2c, b2c) * sconv3(u11, l, w1a, w1b, w1c, b1c);
            int p = PD(l);
            xr[p] = v0; xi[p] = v1;
        }
        for (int l = LL + tid; l < NFFT; l += 512) { int p = PD(l); xr[p] = 0.f; xi[p] = 0.f; }
    }
    __syncthreads();

    for (int sh = 11; sh >= 1; sh -= 2) { dif_pass(xr, xi, twr, twi, sh); __syncthreads(); }

    // middle: DIF h=1 + K multiply + DIT h=1 (bit-reversed bin order)
    {
        const __half2* kf = g_kf + (size_t)d * NFFT;
        for (int t = tid; t < 4096; t += 512) {
            int p0 = PD(2 * t), p1 = PD(2 * t + 1);
            float a_r = xr[p0], a_i = xi[p0], b_r = xr[p1], b_i = xi[p1];
            float er = a_r + b_r, ei = a_i + b_i;
            float orr = a_r - b_r, oi = a_i - b_i;
            float2 K0 = __half22float2(kf[2 * t]);
            float2 K1 = __half22float2(kf[2 * t + 1]);
            float Er = er * K0.x - ei * K0.y,  Ei = er * K0.y + ei * K0.x;
            float Or = orr * K1.x - oi * K1.y, Oi = orr * K1.y + oi * K1.x;
            xr[p0] = Er + Or; xi[p0] = Ei + Oi;
            xr[p1] = Er - Or; xi[p1] = Ei - Oi;
        }
    }
    __syncthreads();

    for (int sh = 1; sh <= 11; sh += 2) { dit_pass(xr, xi, twr, twi, sh); __syncthreads(); }

    // epilogue: recompute x0, v; gate; split bf16; store (b,d,l)
    {
        const float* u00 = g_u + ((size_t)(0 * N3) + d) * LL;
        const float* u10 = g_u + ((size_t)(1 * N3) + d) * LL;
        float w0a = sw[d * 3 + 0], w0b = sw[d * 3 + 1], w0c = sw[d * 3 + 2];
        float w1a = sw[(DD + d) * 3 + 0], w1b = sw[(DD + d) * 3 + 1], w1c = sw[(DD + d) * 3 + 2];
        float w2a = sw[(2 * DD + d) * 3 + 0], w2b = sw[(2 * DD + d) * 3 + 1], w2c = sw[(2 * DD + d) * 3 + 2];
        float b0c = sb[d], b1c = sb[DD + d], b2c = sb[2 * DD + d];
        const float bi = fbias[d];
        const float inv = 1.0f / (float)NFFT;
        __nv_bfloat16* gh0 = g_gh + (size_t)d * LL;
        __nv_bfloat16* gl0 = g_gl + (size_t)d * LL;
        __nv_bfloat16* gh1 = g_gh + ((size_t)DD + d) * LL;
        __nv_bfloat16* gl1 = g_gl + ((size_t)DD + d) * LL;
        for (int l = tid; l < LL; l += 512) {
            int p = PD(l);
            float x0_0 = sconv3(u00, l, w0a, w0b, w0c, b0c);
            float v_0  = sconv3(u02, l, w2a, w2b, w2c, b2c) * sconv3(u01, l, w1a, w1b, w1c, b1c);
            float x0_1 = sconv3(u10, l, w0a, w0b, w0c, b0c);
            float v_1  = sconv3(u12, l, w2a, w2b, w2c, b2c) * sconv3(u11, l, w1a, w1b, w1c, b1c);
            float r0 = (xr[p] * inv + v_0 * bi) * x0_0;
            float r1 = (xi[p] * inv + v_1 * bi) * x0_1;
            __nv_bfloat16 h0 = __float2bfloat16(r0);
            __nv_bfloat16 h1 = __float2bfloat16(r1);
            gh0[l] = h0; gl0[l] = __float2bfloat16(r0 - __bfloat162float(h0));
            gh1[l] = h1; gl1[l] = __float2bfloat16(r1 - __bfloat162float(h1));
        }
    }
}

// ---------------- launch ----------------
extern "C" void kernel_launch(void* const* d_in, const int* in_sizes, int n_in,
                              void* d_out, int out_size)
{
    const float* x    = (const float*)d_in[0];
    const float* iw   = (const float*)d_in[1];
    const float* ib   = (const float*)d_in[2];
    const float* sw   = (const float*)d_in[3];
    const float* sb   = (const float*)d_in[4];
    const float* w0   = (const float*)d_in[5];
    const float* b0   = (const float*)d_in[6];
    const float* fr   = (const float*)d_in[7];
    const float* w1   = (const float*)d_in[8];
    const float* b1   = (const float*)d_in[9];
    const float* w2   = (const float*)d_in[10];
    const float* b2   = (const float*)d_in[11];
    const float* w3   = (const float*)d_in[12];
    const float* fb   = (const float*)d_in[13];
    const float* ow   = (const float*)d_in[14];
    const float* ob   = (const float*)d_in[15];
    float* out = (float*)d_out;

    (void)cudaFuncSetAttribute(k_fft_k,    cudaFuncAttributeMaxDynamicSharedMemorySize, FFT_SMEM);
    (void)cudaFuncSetAttribute(k_fftconv,  cudaFuncAttributeMaxDynamicSharedMemorySize, FFT_SMEM);
    (void)cudaFuncSetAttribute(k_gemm_in,  cudaFuncAttributeMaxDynamicSharedMemorySize, GEMM_SMEM);
    (void)cudaFuncSetAttribute(k_gemm_out, cudaFuncAttributeMaxDynamicSharedMemorySize, GEMM_SMEM);

    __nv_bfloat16 *xh, *xl, *wih, *wil, *gh, *gl, *woh, *wol;
    cudaGetSymbolAddress((void**)&xh,  g_xh);  cudaGetSymbolAddress((void**)&xl,  g_xl);
    cudaGetSymbolAddress((void**)&wih, g_wih); cudaGetSymbolAddress((void**)&wil, g_wil);
    cudaGetSymbolAddress((void**)&gh,  g_gh);  cudaGetSymbolAddress((void**)&gl,  g_gl);
    cudaGetSymbolAddress((void**)&woh, g_woh); cudaGetSymbolAddress((void**)&wol, g_wol);

    int n4;
    n4 = (MROWS * KDIM) / 4;  k_split<<<(n4 + 255) / 256, 256>>>(x,  xh,  xl,  n4);   // 1
    n4 = (N3 * KDIM) / 4;     k_split<<<(n4 + 255) / 256, 256>>>(iw, wih, wil, n4);   // 2
    n4 = (DD * KDIM) / 4;     k_split<<<(n4 + 255) / 256, 256>>>(ow, woh, wol, n4);   // 3
    k_gemm_in<<<dim3(N3 / 128, MROWS / 128), 256, GEMM_SMEM>>>(xh, xl, wih, wil, ib); // 4 (profiled)
    k_twiddle<<<4, 512>>>();                                                          // 5
    k_filter_h<<<LL / 4, 256>>>(w0, b0, fr, w1, b1, w2, b2);                          // 6
    k_filter_k<<<dim3(LL / 64, DD / 64), 256>>>(w3);                                  // 7
    k_fft_k<<<DD / 2, 512, FFT_SMEM>>>();                                             // 8
    k_fftconv<<<DD, 512, FFT_SMEM>>>(sw, sb, fb);                                     // 9
    k_gemm_out<<<dim3(2048 / 128, MROWS / 128), 256, GEMM_SMEM>>>(gh, gl, woh, wol, ob, out); // 10
}

// round 12
// speedup vs baseline: 5.2881x; 1.0441x over previous
#include <cuda_runtime.h>
#include <cuda_bf16.h>
#include <cuda_fp16.h>
#include <cstdint>

// ---------------- problem constants ----------------
#define BB      2
#define DD      2048
#define LL      4096
#define N3      6144          // 3*D
#define NFFT    8192          // 2*L
#define ORD     64            // filter order
#define KDIM    2048          // GEMM K (both GEMMs)
#define MROWS   8192          // GEMM M (B*L)

// GEMM tiling: CTA 128(m) x 256(n), warp 64x64 (2x4 warps), K-chunk 32, 3 stages
#define Bb_K 32
#define NCHUNK (KDIM / Bb_K)          // 64
#define A_BYTES   8192                // 128 rows x 64 B
#define B_BYTES   16384               // 256 rows x 64 B
#define STAGE_BYTES (2 * A_BYTES + 2 * B_BYTES)   // 49152
#define OFF_AL  A_BYTES               // 8192
#define OFF_BH  (2 * A_BYTES)         // 16384
#define OFF_BL  (2 * A_BYTES + B_BYTES) // 32768
#define GEMM_SMEM  (3 * STAGE_BYTES)  // 147456

// FFT smem layout (floats), padded idx = i + (i>>5)
#define PD(i) ((i) + ((i) >> 5))
#define XPAD 8448
#define TPAD 2112
#define FFT_SMEM ((2 * XPAD + 2 * TPAD) * 4)   // 84480 bytes

// ---------------- scratch (device globals) ----------------
__device__ float  g_u [(size_t)BB * N3 * LL];     // in_proj output, (b, c, l)
__device__ float  g_k [(size_t)DD * LL];          // filter k, (d, l)
__device__ float  g_h [(size_t)LL * ORD];         // MLP features h, (l, o)
__device__ __half2 g_kf[(size_t)DD * NFFT];       // K full spectra (DIF order, fp16)
__device__ float2 g_tw2[2048];                    // twiddles e^{-2pi i m/8192}, m<2048

// bf16 split operands
__device__ __nv_bfloat16 g_xh [(size_t)MROWS * KDIM];
__device__ __nv_bfloat16 g_xl [(size_t)MROWS * KDIM];
__device__ __nv_bfloat16 g_wih[(size_t)N3 * KDIM];
__device__ __nv_bfloat16 g_wil[(size_t)N3 * KDIM];
__device__ __nv_bfloat16 g_gh [(size_t)BB * DD * LL];   // gated output, (b,d,l)
__device__ __nv_bfloat16 g_gl [(size_t)BB * DD * LL];
__device__ __nv_bfloat16 g_woh[(size_t)DD * KDIM];
__device__ __nv_bfloat16 g_wol[(size_t)DD * KDIM];

// ---------------- PTX helpers ----------------
__device__ __forceinline__ uint32_t smem_u32(const void* p) {
    uint32_t a;
    asm("{ .reg .u64 t; cvta.to.shared.u64 t, %1; cvt.u32.u64 %0, t; }" : "=r"(a) : "l"(p));
    return a;
}
__device__ __forceinline__ void cpa16(uint32_t dst, const void* src) {
    asm volatile("cp.async.cg.shared.global [%0], [%1], 16;" :: "r"(dst), "l"(src) : "memory");
}
#define CPA_COMMIT() asm volatile("cp.async.commit_group;" ::: "memory")
#define CPA_WAIT1()  asm volatile("cp.async.wait_group 1;" ::: "memory")
#define CPA_WAIT0()  asm volatile("cp.async.wait_group 0;" ::: "memory")

#define LDX4(r, addr) \
    asm volatile("ldmatrix.sync.aligned.m8n8.x4.shared.b16 {%0,%1,%2,%3}, [%4];" \
        : "=r"((r)[0]), "=r"((r)[1]), "=r"((r)[2]), "=r"((r)[3]) : "r"(addr))
#define LDX4T(r, addr) \
    asm volatile("ldmatrix.sync.aligned.m8n8.x4.trans.shared.b16 {%0,%1,%2,%3}, [%4];" \
        : "=r"((r)[0]), "=r"((r)[1]), "=r"((r)[2]), "=r"((r)[3]) : "r"(addr))
#define LDX2(r, addr) \
    asm volatile("ldmatrix.sync.aligned.m8n8.x2.shared.b16 {%0,%1}, [%2];" \
        : "=r"((r)[0]), "=r"((r)[1]) : "r"(addr))

#define MMA16816(d, a, b0, b1) \
    asm volatile("mma.sync.aligned.m16n8k16.row.col.f32.bf16.bf16.f32 " \
        "{%0,%1,%2,%3}, {%4,%5,%6,%7}, {%8,%9}, {%0,%1,%2,%3};" \
        : "+f"((d)[0]), "+f"((d)[1]), "+f"((d)[2]), "+f"((d)[3]) \
        : "r"((a)[0]), "r"((a)[1]), "r"((a)[2]), "r"((a)[3]), "r"(b0), "r"(b1))

__device__ __forceinline__ uint32_t swz(uint32_t off) {
    return off ^ ((off >> 3) & 0x30u);
}
__device__ __forceinline__ int brev13(int x) {
    return (int)(__brev((unsigned)x) >> 19);
}

// ---------------- twiddle table ----------------
__global__ void k_twiddle() {
    int j = blockIdx.x * blockDim.x + threadIdx.x;
    if (j < 2048) {
        double a = -2.0 * 3.14159265358979323846 * (double)j / (double)NFFT;
        g_tw2[j] = make_float2((float)cos(a), (float)sin(a));
    }
}

// ---------------- fp32 -> bf16 hi/lo split ----------------
__global__ void k_split(const float* __restrict__ in, __nv_bfloat16* __restrict__ hi,
                        __nv_bfloat16* __restrict__ lo, int n4)
{
    int i = blockIdx.x * blockDim.x + threadIdx.x;
    if (i >= n4) return;
    float4 v = ((const float4*)in)[i];
    __nv_bfloat16 h0 = __float2bfloat16(v.x), h1 = __float2bfloat16(v.y);
    __nv_bfloat16 h2 = __float2bfloat16(v.z), h3 = __float2bfloat16(v.w);
    __nv_bfloat162 hh0 = {h0, h1}, hh1 = {h2, h3};
    ((__nv_bfloat162*)hi)[i * 2 + 0] = hh0;
    ((__nv_bfloat162*)hi)[i * 2 + 1] = hh1;
    __nv_bfloat162 ll0 = {__float2bfloat16(v.x - __bfloat162float(h0)),
                          __float2bfloat16(v.y - __bfloat162float(h1))};
    __nv_bfloat162 ll1 = {__float2bfloat16(v.z - __bfloat162float(h2)),
                          __float2bfloat16(v.w - __bfloat162float(h3))};
    ((__nv_bfloat162*)lo)[i * 2 + 0] = ll0;
    ((__nv_bfloat162*)lo)[i * 2 + 1] = ll1;
}

// ================= GEMM 1: in_proj, CTA 128x256, warp 64x64 =================
__global__ __launch_bounds__(256, 1)
void k_gemm_in(const __nv_bfloat16* __restrict__ Ah, const __nv_bfloat16* __restrict__ Al,
               const __nv_bfloat16* __restrict__ Bh, const __nv_bfloat16* __restrict__ Bl,
               const float* __restrict__ bias)
{
    extern __shared__ __align__(128) unsigned char dsm[];
    const uint32_t sb = smem_u32(dsm);
    const int tid  = threadIdx.x;
    const int lane = tid & 31;
    const int wid  = tid >> 5;
    const int wm   = wid >> 2;         // 0..1
    const int wn   = wid & 3;          // 0..3
    const int m0 = blockIdx.y * 128;
    const int n0 = blockIdx.x * 256;

    // cp.async: row = tid>>2 (+64r), c = tid&3
    const int rw = tid >> 2, cw = tid & 3;
    const uint32_t so0 = swz((uint32_t)(rw * 64 + cw * 16));
    const __nv_bfloat16* pAh = Ah + (size_t)(m0 + rw) * KDIM + cw * 8;
    const __nv_bfloat16* pAl = Al + (size_t)(m0 + rw) * KDIM + cw * 8;
    const __nv_bfloat16* pBh = Bh + (size_t)(n0 + rw) * KDIM + cw * 8;
    const __nv_bfloat16* pBl = Bl + (size_t)(n0 + rw) * KDIM + cw * 8;
    const size_t RB = (size_t)64 * KDIM;   // +64 rows

#define LOADST(st, k0) do {                                                   \
        uint32_t base = sb + (uint32_t)(st) * STAGE_BYTES;                    \
        cpa16(base + so0,                    pAh + (k0));                     \
        cpa16(base + so0 + 4096,             pAh + (k0) + RB);                \
        cpa16(base + OFF_AL + so0,           pAl + (k0));                     \
        cpa16(base + OFF_AL + so0 + 4096,    pAl + (k0) + RB);                \
        cpa16(base + OFF_BH + so0,           pBh + (k0));                     \
        cpa16(base + OFF_BH + so0 + 4096,    pBh + (k0) + RB);                \
        cpa16(base + OFF_BH + so0 + 8192,    pBh + (k0) + 2 * RB);            \
        cpa16(base + OFF_BH + so0 + 12288,   pBh + (k0) + 3 * RB);            \
        cpa16(base + OFF_BL + so0,           pBl + (k0));                     \
        cpa16(base + OFF_BL + so0 + 4096,    pBl + (k0) + RB);                \
        cpa16(base + OFF_BL + so0 + 8192,    pBl + (k0) + 2 * RB);            \
        cpa16(base + OFF_BL + so0 + 12288,   pBl + (k0) + 3 * RB);            \
        CPA_COMMIT();                                                         \
    } while (0)

    uint32_t aoff[4], boff[8];
    {
        int ra = lane & 15, ka = (lane >> 4) * 16;
        int rb = lane & 7,  kb = ((lane >> 3) & 1) * 16;
#pragma unroll
        for (int mi = 0; mi < 4; mi++)
            aoff[mi] = swz((uint32_t)((wm * 64 + mi * 16 + ra) * 64 + ka));
#pragma unroll
        for (int ni = 0; ni < 8; ni++)
            boff[ni] = swz((uint32_t)((wn * 64 + ni * 8 + rb) * 64 + kb));
    }

    float acc[4][8][4];
#pragma unroll
    for (int mi = 0; mi < 4; mi++)
#pragma unroll
        for (int ni = 0; ni < 8; ni++)
#pragma unroll
            for (int r = 0; r < 4; r++) acc[mi][ni][r] = 0.f;

    LOADST(0, 0);
    LOADST(1, Bb_K);

    for (int i = 0; i < NCHUNK; i++) {
        if (i + 1 < NCHUNK) { CPA_WAIT1(); } else { CPA_WAIT0(); }
        __syncthreads();
        if (i + 2 < NCHUNK) LOADST((i + 2) % 3, (i + 2) * Bb_K);

        uint32_t base = sb + (uint32_t)(i % 3) * STAGE_BYTES;
#pragma unroll
        for (int s = 0; s < 2; s++) {
            // NOTE: pre-swz offsets have bit5 clear, so swz(off + s*32) == swz(off) ^ (s*32)
            const uint32_t sx = (uint32_t)(s * 32);
            uint32_t ah[4][4], al[4][4], bh[8][2], bl[8][2];
#pragma unroll
            for (int mi = 0; mi < 4; mi++) {
                LDX4(ah[mi], base + (aoff[mi] ^ sx));
                LDX4(al[mi], base + OFF_AL + (aoff[mi] ^ sx));
            }
#pragma unroll
            for (int ni = 0; ni < 8; ni++) {
                LDX2(bh[ni], base + OFF_BH + (boff[ni] ^ sx));
                LDX2(bl[ni], base + OFF_BL + (boff[ni] ^ sx));
            }
#pragma unroll
            for (int mi = 0; mi < 4; mi++)
#pragma unroll
                for (int ni = 0; ni < 8; ni++) {
                    MMA16816(acc[mi][ni], ah[mi], bh[ni][0], bh[ni][1]);
                    MMA16816(acc[mi][ni], ah[mi], bl[ni][0], bl[ni][1]);
                    MMA16816(acc[mi][ni], al[mi], bh[ni][0], bh[ni][1]);
                }
        }
    }
#undef LOADST
    __syncthreads();

    // epilogue: transpose via smem [256 n][132], store (b,c,l)
    float* ep = (float*)dsm;
    const int r  = lane >> 2;
    const int cc = 2 * (lane & 3);
#pragma unroll
    for (int mi = 0; mi < 4; mi++)
#pragma unroll
        for (int ni = 0; ni < 8; ni++) {
            int mloc = wm * 64 + mi * 16 + r;
            int nloc = wn * 64 + ni * 8 + cc;
            const float* a = acc[mi][ni];
            ep[nloc * 132 + mloc]           = a[0];
            ep[(nloc + 1) * 132 + mloc]     = a[1];
            ep[nloc * 132 + mloc + 8]       = a[2];
            ep[(nloc + 1) * 132 + mloc + 8] = a[3];
        }
    __syncthreads();

    const float* src = ep + tid * 132;
    const int b  = m0 >> 12;
    const int l0 = m0 & (LL - 1);
    const float bi = bias[n0 + tid];
    float* dst = g_u + ((size_t)b * N3 + n0 + tid) * LL + l0;
#pragma unroll
    for (int j = 0; j < 32; j++) {
        float4 v = *(const float4*)(src + j * 4);
        v.x += bi; v.y += bi; v.z += bi; v.w += bi;
        *(float4*)(dst + j * 4) = v;
    }
}

// ================= GEMM 2: out_proj, CTA 128x256, warp 64x64, A trans =================
__global__ __launch_bounds__(256, 1)
void k_gemm_out(const __nv_bfloat16* __restrict__ Ah, const __nv_bfloat16* __restrict__ Al,
                const __nv_bfloat16* __restrict__ Bh, const __nv_bfloat16* __restrict__ Bl,
                const float* __restrict__ bias, float* __restrict__ Out)
{
    extern __shared__ __align__(128) unsigned char dsm[];
    const uint32_t sb = smem_u32(dsm);
    const int tid  = threadIdx.x;
    const int lane = tid & 31;
    const int wid  = tid >> 5;
    const int wm   = wid >> 2;
    const int wn   = wid & 3;
    const int m0 = blockIdx.y * 128;
    const int n0 = blockIdx.x * 256;
    const int bb = m0 >> 12;
    const int l0 = m0 & (LL - 1);

    // A (trans): tile [32 k][128 m], row = k (256B), xor swizzle
    const int rA = tid >> 4, cA = tid & 15;
    const uint32_t soA = (uint32_t)(rA * 256 + ((cA ^ (rA & 7)) << 4));
    const __nv_bfloat16* pAh = Ah + ((size_t)bb * DD + rA) * LL + l0 + cA * 8;
    const __nv_bfloat16* pAl = Al + ((size_t)bb * DD + rA) * LL + l0 + cA * 8;
    const size_t RA = (size_t)16 * LL;

    // B: 256 rows x 64 B
    const int rw = tid >> 2, cw = tid & 3;
    const uint32_t so0 = swz((uint32_t)(rw * 64 + cw * 16));
    const __nv_bfloat16* pBh = Bh + (size_t)(n0 + rw) * KDIM + cw * 8;
    const __nv_bfloat16* pBl = Bl + (size_t)(n0 + rw) * KDIM + cw * 8;
    const size_t RB = (size_t)64 * KDIM;

#define LOADST2(st, ci) do {                                                  \
        uint32_t base = sb + (uint32_t)(st) * STAGE_BYTES;                    \
        size_t ko = (size_t)(ci) * Bb_K * LL;                                 \
        int kb = (ci) * Bb_K;                                                 \
        cpa16(base + soA,                    pAh + ko);                       \
        cpa16(base + soA + 4096,             pAh + ko + RA);                  \
        cpa16(base + OFF_AL + soA,           pAl + ko);                       \
        cpa16(base + OFF_AL + soA + 4096,    pAl + ko + RA);                  \
        cpa16(base + OFF_BH + so0,           pBh + kb);                       \
        cpa16(base + OFF_BH + so0 + 4096,    pBh + kb + RB);                  \
        cpa16(base + OFF_BH + so0 + 8192,    pBh + kb + 2 * RB);              \
        cpa16(base + OFF_BH + so0 + 12288,   pBh + kb + 3 * RB);              \
        cpa16(base + OFF_BL + so0,           pBl + kb);                       \
        cpa16(base + OFF_BL + so0 + 4096,    pBl + kb + RB);                  \
        cpa16(base + OFF_BL + so0 + 8192,    pBl + kb + 2 * RB);              \
        cpa16(base + OFF_BL + so0 + 12288,   pBl + kb + 3 * RB);              \
        CPA_COMMIT();                                                         \
    } while (0)

    uint32_t aoffT[4][2], boff[8];
    {
        int kr = (lane & 7) + ((lane >> 4) << 3);
        int msub = ((lane >> 3) & 1) * 8;
        int rb = lane & 7, kb = ((lane >> 3) & 1) * 16;
#pragma unroll
        for (int mi = 0; mi < 4; mi++)
#pragma unroll
            for (int s = 0; s < 2; s++) {
                int row = s * 16 + kr;
                int mcChunk = (wm * 64 + mi * 16 + msub) >> 3;
                aoffT[mi][s] = (uint32_t)(row * 256 + ((mcChunk ^ (row & 7)) << 4));
            }
#pragma unroll
        for (int ni = 0; ni < 8; ni++)
            boff[ni] = swz((uint32_t)((wn * 64 + ni * 8 + rb) * 64 + kb));
    }

    float acc[4][8][4];
#pragma unroll
    for (int mi = 0; mi < 4; mi++)
#pragma unroll
        for (int ni = 0; ni < 8; ni++)
#pragma unroll
            for (int r = 0; r < 4; r++) acc[mi][ni][r] = 0.f;

    LOADST2(0, 0);
    LOADST2(1, 1);

    for (int i = 0; i < NCHUNK; i++) {
        if (i + 1 < NCHUNK) { CPA_WAIT1(); } else { CPA_WAIT0(); }
        __syncthreads();
        if (i + 2 < NCHUNK) LOADST2((i + 2) % 3, i + 2);

        uint32_t base = sb + (uint32_t)(i % 3) * STAGE_BYTES;
#pragma unroll
        for (int s = 0; s < 2; s++) {
            const uint32_t sx = (uint32_t)(s * 32);
            uint32_t ah[4][4], al[4][4], bh[8][2], bl[8][2];
#pragma unroll
            for (int mi = 0; mi < 4; mi++) {
                LDX4T(ah[mi], base + aoffT[mi][s]);
                LDX4T(al[mi], base + OFF_AL + aoffT[mi][s]);
            }
#pragma unroll
            for (int ni = 0; ni < 8; ni++) {
                LDX2(bh[ni], base + OFF_BH + (boff[ni] ^ sx));
                LDX2(bl[ni], base + OFF_BL + (boff[ni] ^ sx));
            }
#pragma unroll
            for (int mi = 0; mi < 4; mi++)
#pragma unroll
                for (int ni = 0; ni < 8; ni++) {
                    MMA16816(acc[mi][ni], ah[mi], bh[ni][0], bh[ni][1]);
                    MMA16816(acc[mi][ni], ah[mi], bl[ni][0], bl[ni][1]);
                    MMA16816(acc[mi][ni], al[mi], bh[ni][0], bh[ni][1]);
                }
        }
    }
#undef LOADST2
    __syncthreads();

    // epilogue: smem [128 m][260], row-major store
    float* ep = (float*)dsm;
    const int r  = lane >> 2;
    const int cc = 2 * (lane & 3);
#pragma unroll
    for (int mi = 0; mi < 4; mi++)
#pragma unroll
        for (int ni = 0; ni < 8; ni++) {
            int mloc = wm * 64 + mi * 16 + r;
            int nloc = wn * 64 + ni * 8 + cc;
            const float* a = acc[mi][ni];
            ep[mloc * 260 + nloc]           = a[0];
            ep[mloc * 260 + nloc + 1]       = a[1];
            ep[(mloc + 8) * 260 + nloc]     = a[2];
            ep[(mloc + 8) * 260 + nloc + 1] = a[3];
        }
    __syncthreads();

    const int erow = tid >> 1;
    const int half = tid & 1;
    const float* src = ep + erow * 260 + half * 128;
    float* dst = Out + (size_t)(m0 + erow) * 2048 + n0 + half * 128;
    const float* bp = bias + n0 + half * 128;
#pragma unroll
    for (int j = 0; j < 32; j++) {
        float4 v = *(const float4*)(src + j * 4);
        float4 bv = *(const float4*)(bp + j * 4);
        v.x += bv.x; v.y += bv.y; v.z += bv.z; v.w += bv.w;
        *(float4*)(dst + j * 4) = v;
    }
}

// ---------------- filter MLP features h(l) ----------------
__global__ __launch_bounds__(256)
void k_filter_h(const float* __restrict__ w0, const float* __restrict__ b0,
                const float* __restrict__ fr,
                const float* __restrict__ w1, const float* __restrict__ b1,
                const float* __restrict__ w2, const float* __restrict__ b2)
{
    __shared__ float hb[2][4][ORD];
    int o  = threadIdx.x & 63;
    int sl = threadIdx.x >> 6;
    int l  = blockIdx.x * 4 + sl;

    float t    = (float)l * (1.0f / (LL - 1));
    float wang = 6.28318530717958647692f * (float)l * (1.0f / LL);
    float ang  = 1e-4f * wang;
    float z0 = t, z1 = cosf(ang), z2 = -sinf(ang);
    float f = fr[o];

    float h = sinf(f * (w0[o * 3 + 0] * z0 + w0[o * 3 + 1] * z1 + w0[o * 3 + 2] * z2 + b0[o]));
    hb[0][sl][o] = h;
    __syncthreads();

    float acc = b1[o];
#pragma unroll
    for (int j = 0; j < ORD; j++) acc += w1[o * ORD + j] * hb[0][sl][j];
    h = sinf(f * acc);
    hb[1][sl][o] = h;
    __syncthreads();

    acc = b2[o];
#pragma unroll
    for (int j = 0; j < ORD; j++) acc += w2[o * ORD + j] * hb[1][sl][j];
    h = sinf(f * acc);
    g_h[(size_t)l * ORD + o] = h;
}

// ---------------- filter k(d,l) ----------------
#define MIN_DECAY (-3.0701134573253937f)
#define MAX_DECAY (-15.350567286626969f)
__global__ __launch_bounds__(256)
void k_filter_k(const float* __restrict__ W3)
{
    __shared__ float hs[64][65];
    __shared__ float ws[64][64];
    int l0 = blockIdx.x * 64;
    int d0 = blockIdx.y * 64;
    for (int i = threadIdx.x; i < 64 * 64; i += 256) {
        int r = i >> 6, cidx = i & 63;
        hs[r][cidx] = g_h[(size_t)(l0 + r) * ORD + cidx];
        ws[r][cidx] = W3[(size_t)(d0 + r) * ORD + cidx];
    }
    __syncthreads();
    for (int i = threadIdx.x; i < 64 * 64; i += 256) {
        int ll = i & 63;
        int dd = i >> 6;
        float acc = 0.f;
#pragma unroll
        for (int j = 0; j < ORD; j++) acc += ws[dd][j] * hs[ll][j];
        int d = d0 + dd, l = l0 + ll;
        float delta = MIN_DECAY + (MAX_DECAY - MIN_DECAY) * (float)d * (1.0f / (DD - 1));
        float decay = expf(-((float)l * (1.0f / (LL - 1))) * fabsf(delta));
        g_k[(size_t)d * LL + l] = acc * decay;
    }
}

// ================= FFT passes (padded split re/im, fused radix-2 pairs) =================
__device__ __forceinline__ void dif_pass(float* xr, float* xi,
                                         const float* twr, const float* twi, int sh)
{
    const int tid = threadIdx.x;
    const int Hh = 1 << sh;
    for (int t = tid; t < 2048; t += 512) {
        int j = t & (Hh - 1);
        int g = t >> sh;
        int i0 = (g << (sh + 2)) + j;
        int p0 = PD(i0), p1 = PD(i0 + Hh), p2 = PD(i0 + 2 * Hh), p3 = PD(i0 + 3 * Hh);
        float x0r = xr[p0], x0i = xi[p0], x1r = xr[p1], x1i = xi[p1];
        float x2r = xr[p2], x2i = xi[p2], x3r = xr[p3], x3i = xi[p3];
        int ti = PD(j << (11 - sh));
        float wr = twr[ti], wi = twi[ti];
        float u0r = x0r + x2r, u0i = x0i + x2i;
        float d0r = x0r - x2r, d0i = x0i - x2i;
        float u2r = d0r * wr - d0i * wi, u2i = d0r * wi + d0i * wr;
        float u1r = x1r + x3r, u1i = x1i + x3i;
        float d1r = x1r - x3r, d1i = x1i - x3i;
        float u3r = d1r * wi + d1i * wr;
        float u3i = d1i * wi - d1r * wr;
        float br = wr * wr - wi * wi, bi = 2.f * wr * wi;
        xr[p0] = u0r + u1r; xi[p0] = u0i + u1i;
        float e0r = u0r - u1r, e0i = u0i - u1i;
        xr[p1] = e0r * br - e0i * bi; xi[p1] = e0r * bi + e0i * br;
        xr[p2] = u2r + u3r; xi[p2] = u2i + u3i;
        float e1r = u2r - u3r, e1i = u2i - u3i;
        xr[p3] = e1r * br - e1i * bi; xi[p3] = e1r * bi + e1i * br;
    }
}

__device__ __forceinline__ void dit_pass(float* xr, float* xi,
                                         const float* twr, const float* twi, int sh)
{
    const int tid = threadIdx.x;
    const int h = 1 << sh;
    for (int t = tid; t < 2048; t += 512) {
        int j = t & (h - 1);
        int g = t >> sh;
        int i0 = (g << (sh + 2)) + j;
        int p0 = PD(i0), p1 = PD(i0 + h), p2 = PD(i0 + 2 * h), p3 = PD(i0 + 3 * h);
        float x0r = xr[p0], x0i = xi[p0], x1r = xr[p1], x1i = xi[p1];
        float x2r = xr[p2], x2i = xi[p2], x3r = xr[p3], x3i = xi[p3];
        int ti = PD(j << (11 - sh));
        float ar = twr[ti], ai = -twi[ti];
        float vr = ar * ar - ai * ai, vi = 2.f * ar * ai;
        float m1r = x1r * vr - x1i * vi, m1i = x1r * vi + x1i * vr;
        float t0r = x0r + m1r, t0i = x0i + m1i;
        float t1r = x0r - m1r, t1i = x0i - m1i;
        float m3r = x3r * vr - x3i * vi, m3i = x3r * vi + x3i * vr;
        float t2r = x2r + m3r, t2i = x2i + m3i;
        float t3r = x2r - m3r, t3i = x2i - m3i;
        float q2r = t2r * ar - t2i * ai, q2i = t2r * ai + t2i * ar;
        xr[p0] = t0r + q2r; xi[p0] = t0i + q2i;
        xr[p2] = t0r - q2r; xi[p2] = t0i - q2i;
        float q3r = -t3r * ai - t3i * ar;
        float q3i =  t3r * ar - t3i * ai;
        xr[p1] = t1r + q3r; xi[p1] = t1i + q3i;
        xr[p3] = t1r - q3r; xi[p3] = t1i - q3i;
    }
}

// ---------------- FFT of filter rows: 2 rows packed per block -> fp16 spectra ----------------
__global__ __launch_bounds__(512, 2) void k_fft_k()
{
    extern __shared__ float fsm[];
    float* xr  = fsm;
    float* xi  = xr + XPAD;
    float* twr = xi + XPAD;
    float* twi = twr + TPAD;
    const int d  = blockIdx.x;          // 0..1023
    const int d2 = d + DD / 2;
    const int tid = threadIdx.x;

    for (int j = tid; j < 2048; j += 512) {
        float2 w = g_tw2[j];
        int p = PD(j);
        twr[p] = w.x; twi[p] = w.y;
    }
    const float* k0 = g_k + (size_t)d  * LL;
    const float* k1 = g_k + (size_t)d2 * LL;
    for (int l = tid; l < LL; l += 512) { int p = PD(l); xr[p] = k0[l]; xi[p] = k1[l]; }
    for (int l = LL + tid; l < NFFT; l += 512) { int p = PD(l); xr[p] = 0.f; xi[p] = 0.f; }
    __syncthreads();

    for (int sh = 11; sh >= 1; sh -= 2) { dif_pass(xr, xi, twr, twi, sh); __syncthreads(); }

    for (int t = tid; t < 4096; t += 512) {
        int p0 = PD(2 * t), p1 = PD(2 * t + 1);
        float a_r = xr[p0], a_i = xi[p0], b_r = xr[p1], b_i = xi[p1];
        xr[p0] = a_r + b_r; xi[p0] = a_i + b_i;
        xr[p1] = a_r - b_r; xi[p1] = a_i - b_i;
    }
    __syncthreads();

    __half2* kfa = g_kf + (size_t)d  * NFFT;
    __half2* kfb = g_kf + (size_t)d2 * NFFT;
    for (int p = tid; p < NFFT; p += 512) {
        int j  = brev13(p);
        int q  = brev13((NFFT - j) & (NFFT - 1));
        int pp = PD(p), pq = PD(q);
        float zpr = xr[pp], zpi = xi[pp];
        float zqr = xr[pq], zqi = xi[pq];
        float ar = 0.5f * (zpr + zqr), ai = 0.5f * (zpi - zqi);
        float br = 0.5f * (zpi + zqi), bi = 0.5f * (zqr - zpr);
        kfa[p] = __floats2half2_rn(ar, ai);
        kfb[p] = __floats2half2_rn(br, bi);
    }
}

// ---------------- fused: short conv + gate + FFT conv + gate + bf16 split ----------------
__device__ __forceinline__ float sconv3(const float* __restrict__ u, int l,
                                        float wa, float wb, float wc, float bs)
{
    float acc = bs + wc * u[l];
    if (l >= 1) acc += wb * u[l - 1];
    if (l >= 2) acc += wa * u[l - 2];
    return acc;
}

__global__ __launch_bounds__(512, 2)
void k_fftconv(const float* __restrict__ sw, const float* __restrict__ sb,
               const float* __restrict__ fbias)
{
    extern __shared__ float fsm[];
    float* xr  = fsm;
    float* xi  = xr + XPAD;
    float* twr = xi + XPAD;
    float* twi = twr + TPAD;
    const int d = blockIdx.x;
    const int tid = threadIdx.x;

    for (int j = tid; j < 2048; j += 512) {
        float2 w = g_tw2[j];
        int p = PD(j);
        twr[p] = w.x; twi[p] = w.y;
    }

    const float* u01 = g_u + ((size_t)(0 * N3 + DD) + d) * LL;
    const float* u02 = g_u + ((size_t)(0 * N3 + 2 * DD) + d) * LL;
    const float* u11 = g_u + ((size_t)(1 * N3 + DD) + d) * LL;
    const float* u12 = g_u + ((size_t)(1 * N3 + 2 * DD) + d) * LL;

    {
        float w1a = sw[(DD + d) * 3 + 0], w1b = sw[(DD + d) * 3 + 1], w1c = sw[(DD + d) * 3 + 2];
        float w2a = sw[(2 * DD + d) * 3 + 0], w2b = sw[(2 * DD + d) * 3 + 1], w2c = sw[(2 * DD + d) * 3 + 2];
        float b1c = sb[DD + d], b2c = sb[2 * DD + d];
        for (int l = tid; l < LL; l += 512) {
            float v0 = sconv3(u02, l, w2a, w2b, w2c, b2c) * sconv3(u01, l, w1a, w1b, w1c, b1c);
            float v1 = sconv3(u12, l, w2a, w2b, w2c, b2c) * sconv3(u11, l, w1a, w1b, w1c, b1c);
            int p = PD(l);
            xr[p] = v0; xi[p] = v1;
        }
        for (int l = LL + tid; l < NFFT; l += 512) { int p = PD(l); xr[p] = 0.f; xi[p] = 0.f; }
    }
    __syncthreads();

    for (int sh = 11; sh >= 1; sh -= 2) { dif_pass(xr, xi, twr, twi, sh); __syncthreads(); }

    {
        const __half2* kf = g_kf + (size_t)d * NFFT;
        for (int t = tid; t < 4096; t += 512) {
            int p0 = PD(2 * t), p1 = PD(2 * t + 1);
            float a_r = xr[p0], a_i = xi[p0], b_r = xr[p1], b_i = xi[p1];
            float er = a_r + b_r, ei = a_i + b_i;
            float orr = a_r - b_r, oi = a_i - b_i;
            float2 K0 = __half22float2(kf[2 * t]);
            float2 K1 = __half22float2(kf[2 * t + 1]);
            float Er = er * K0.x - ei * K0.y,  Ei = er * K0.y + ei * K0.x;
            float Or = orr * K1.x - oi * K1.y, Oi = orr * K1.y + oi * K1.x;
            xr[p0] = Er + Or; xi[p0] = Ei + Oi;
            xr[p1] = Er - Or; xi[p1] = Ei - Oi;
        }
    }
    __syncthreads();

    for (int sh = 1; sh <= 11; sh += 2) { dit_pass(xr, xi, twr, twi, sh); __syncthreads(); }

    {
        const float* u00 = g_u + ((size_t)(0 * N3) + d) * LL;
        const float* u10 = g_u + ((size_t)(1 * N3) + d) * LL;
        float w0a = sw[d * 3 + 0], w0b = sw[d * 3 + 1], w0c = sw[d * 3 + 2];
        float w1a = sw[(DD + d) * 3 + 0], w1b = sw[(DD + d) * 3 + 1], w1c = sw[(DD + d) * 3 + 2];
        float w2a = sw[(2 * DD + d) * 3 + 0], w2b = sw[(2 * DD + d) * 3 + 1], w2c = sw[(2 * DD + d) * 3 + 2];
        float b0c = sb[d], b1c = sb[DD + d], b2c = sb[2 * DD + d];
        const float bi = fbias[d];
        const float inv = 1.0f / (float)NFFT;
        __nv_bfloat16* gh0 = g_gh + (size_t)d * LL;
        __nv_bfloat16* gl0 = g_gl + (size_t)d * LL;
        __nv_bfloat16* gh1 = g_gh + ((size_t)DD + d) * LL;
        __nv_bfloat16* gl1 = g_gl + ((size_t)DD + d) * LL;
        for (int l = tid; l < LL; l += 512) {
            int p = PD(l);
            float x0_0 = sconv3(u00, l, w0a, w0b, w0c, b0c);
            float v_0  = sconv3(u02, l, w2a, w2b, w2c, b2c) * sconv3(u01, l, w1a, w1b, w1c, b1c);
            float x0_1 = sconv3(u10, l, w0a, w0b, w0c, b0c);
            float v_1  = sconv3(u12, l, w2a, w2b, w2c, b2c) * sconv3(u11, l, w1a, w1b, w1c, b1c);
            float r0 = (xr[p] * inv + v_0 * bi) * x0_0;
            float r1 = (xi[p] * inv + v_1 * bi) * x0_1;
            __nv_bfloat16 h0 = __float2bfloat16(r0);
            __nv_bfloat16 h1 = __float2bfloat16(r1);
            gh0[l] = h0; gl0[l] = __float2bfloat16(r0 - __bfloat162float(h0));
            gh1[l] = h1; gl1[l] = __float2bfloat16(r1 - __bfloat162float(h1));
        }
    }
}

// ---------------- launch ----------------
extern "C" void kernel_launch(void* const* d_in, const int* in_sizes, int n_in,
                              void* d_out, int out_size)
{
    const float* x    = (const float*)d_in[0];
    const float* iw   = (const float*)d_in[1];
    const float* ib   = (const float*)d_in[2];
    const float* sw   = (const float*)d_in[3];
    const float* sb   = (const float*)d_in[4];
    const float* w0   = (const float*)d_in[5];
    const float* b0   = (const float*)d_in[6];
    const float* fr   = (const float*)d_in[7];
    const float* w1   = (const float*)d_in[8];
    const float* b1   = (const float*)d_in[9];
    const float* w2   = (const float*)d_in[10];
    const float* b2   = (const float*)d_in[11];
    const float* w3   = (const float*)d_in[12];
    const float* fb   = (const float*)d_in[13];
    const float* ow   = (const float*)d_in[14];
    const float* ob   = (const float*)d_in[15];
    float* out = (float*)d_out;

    (void)cudaFuncSetAttribute(k_fft_k,    cudaFuncAttributeMaxDynamicSharedMemorySize, FFT_SMEM);
    (void)cudaFuncSetAttribute(k_fftconv,  cudaFuncAttributeMaxDynamicSharedMemorySize, FFT_SMEM);
    (void)cudaFuncSetAttribute(k_gemm_in,  cudaFuncAttributeMaxDynamicSharedMemorySize, GEMM_SMEM);
    (void)cudaFuncSetAttribute(k_gemm_out, cudaFuncAttributeMaxDynamicSharedMemorySize, GEMM_SMEM);

    __nv_bfloat16 *xh, *xl, *wih, *wil, *gh, *gl, *woh, *wol;
    cudaGetSymbolAddress((void**)&xh,  g_xh);  cudaGetSymbolAddress((void**)&xl,  g_xl);
    cudaGetSymbolAddress((void**)&wih, g_wih); cudaGetSymbolAddress((void**)&wil, g_wil);
    cudaGetSymbolAddress((void**)&gh,  g_gh);  cudaGetSymbolAddress((void**)&gl,  g_gl);
    cudaGetSymbolAddress((void**)&woh, g_woh); cudaGetSymbolAddress((void**)&wol, g_wol);

    int n4;
    n4 = (MROWS * KDIM) / 4;  k_split<<<(n4 + 255) / 256, 256>>>(x,  xh,  xl,  n4);   // 1
    n4 = (N3 * KDIM) / 4;     k_split<<<(n4 + 255) / 256, 256>>>(iw, wih, wil, n4);   // 2
    n4 = (DD * KDIM) / 4;     k_split<<<(n4 + 255) / 256, 256>>>(ow, woh, wol, n4);   // 3
    k_gemm_in<<<dim3(N3 / 256, MROWS / 128), 256, GEMM_SMEM>>>(xh, xl, wih, wil, ib); // 4 (profiled)
    k_twiddle<<<4, 512>>>();                                                          // 5
    k_filter_h<<<LL / 4, 256>>>(w0, b0, fr, w1, b1, w2, b2);                          // 6
    k_filter_k<<<dim3(LL / 64, DD / 64), 256>>>(w3);                                  // 7
    k_fft_k<<<DD / 2, 512, FFT_SMEM>>>();                                             // 8
    k_fftconv<<<DD, 512, FFT_SMEM>>>(sw, sb, fb);                                     // 9
    k_gemm_out<<<dim3(2048 / 256, MROWS / 128), 256, GEMM_SMEM>>>(gh, gl, woh, wol, ob, out); // 10
}

// round 13
// speedup vs baseline: 6.8583x; 1.2969x over previous
#include <cuda_runtime.h>
#include <cuda_bf16.h>
#include <cuda_fp16.h>
#include <cstdint>

// ---------------- problem constants ----------------
#define BB      2
#define DD      2048
#define LL      4096
#define N3      6144          // 3*D
#define NFFT    8192          // 2*L
#define ORD     64            // filter order
#define KDIM    2048          // GEMM K (both GEMMs)
#define MROWS   8192          // GEMM M (B*L)

// GEMM tiling: CTA 128(m) x 256(n), warp 64x64 (2x4 warps), K-chunk 32, 4 stages
// Operands: A split into fp16 hi+lo, B single fp16 -> 2 MMAs per (mi,ni,s)
#define Bb_K 32
#define NCHUNK (KDIM / Bb_K)          // 64
#define A_BYTES   8192                // 128 rows x 64 B
#define B_BYTES   16384               // 256 rows x 64 B
#define OFF_AL  A_BYTES               // 8192
#define OFF_B   (2 * A_BYTES)         // 16384
#define STAGE_BYTES (2 * A_BYTES + B_BYTES)   // 32768
#define GEMM_SMEM  135168             // max(4*STAGE=131072, epilogue 256*132*4=135168)

// FFT smem layout (floats), padded idx = i + (i>>5)
#define PD(i) ((i) + ((i) >> 5))
#define XPAD 8448
#define TPAD 2112
#define FFT_SMEM ((2 * XPAD + 2 * TPAD) * 4)   // 84480 bytes

// ---------------- scratch (device globals) ----------------
__device__ float  g_u [(size_t)BB * N3 * LL];     // in_proj output, (b, c, l)
__device__ float  g_k [(size_t)DD * LL];          // filter k, (d, l)
__device__ float  g_h [(size_t)LL * ORD];         // MLP features h, (l, o)
__device__ __half2 g_kf[(size_t)DD * NFFT];       // K full spectra (DIF order, fp16)
__device__ float2 g_tw2[2048];                    // twiddles e^{-2pi i m/8192}, m<2048

// fp16 GEMM operands
__device__ __half g_xh [(size_t)MROWS * KDIM];    // x hi
__device__ __half g_xl [(size_t)MROWS * KDIM];    // x lo
__device__ __half g_wi [(size_t)N3 * KDIM];       // in_proj W (single)
__device__ __half g_gh [(size_t)BB * DD * LL];    // gated output hi, (b,d,l)
__device__ __half g_gl [(size_t)BB * DD * LL];    // gated output lo
__device__ __half g_wo [(size_t)DD * KDIM];       // out_proj W (single)

// ---------------- PTX helpers ----------------
__device__ __forceinline__ uint32_t smem_u32(const void* p) {
    uint32_t a;
    asm("{ .reg .u64 t; cvta.to.shared.u64 t, %1; cvt.u32.u64 %0, t; }" : "=r"(a) : "l"(p));
    return a;
}
__device__ __forceinline__ void cpa16(uint32_t dst, const void* src) {
    asm volatile("cp.async.cg.shared.global [%0], [%1], 16;" :: "r"(dst), "l"(src) : "memory");
}
#define CPA_COMMIT() asm volatile("cp.async.commit_group;" ::: "memory")
#define CPA_WAIT2()  asm volatile("cp.async.wait_group 2;" ::: "memory")
#define CPA_WAIT1()  asm volatile("cp.async.wait_group 1;" ::: "memory")
#define CPA_WAIT0()  asm volatile("cp.async.wait_group 0;" ::: "memory")

#define LDX4(r, addr) \
    asm volatile("ldmatrix.sync.aligned.m8n8.x4.shared.b16 {%0,%1,%2,%3}, [%4];" \
        : "=r"((r)[0]), "=r"((r)[1]), "=r"((r)[2]), "=r"((r)[3]) : "r"(addr))
#define LDX4T(r, addr) \
    asm volatile("ldmatrix.sync.aligned.m8n8.x4.trans.shared.b16 {%0,%1,%2,%3}, [%4];" \
        : "=r"((r)[0]), "=r"((r)[1]), "=r"((r)[2]), "=r"((r)[3]) : "r"(addr))
#define LDX2(r, addr) \
    asm volatile("ldmatrix.sync.aligned.m8n8.x2.shared.b16 {%0,%1}, [%2];" \
        : "=r"((r)[0]), "=r"((r)[1]) : "r"(addr))

// fp16 inputs, fp32 accumulate
#define MMA16816H(d, a, b0, b1) \
    asm volatile("mma.sync.aligned.m16n8k16.row.col.f32.f16.f16.f32 " \
        "{%0,%1,%2,%3}, {%4,%5,%6,%7}, {%8,%9}, {%0,%1,%2,%3};" \
        : "+f"((d)[0]), "+f"((d)[1]), "+f"((d)[2]), "+f"((d)[3]) \
        : "r"((a)[0]), "r"((a)[1]), "r"((a)[2]), "r"((a)[3]), "r"(b0), "r"(b1))

__device__ __forceinline__ uint32_t swz(uint32_t off) {
    return off ^ ((off >> 3) & 0x30u);
}
__device__ __forceinline__ int brev13(int x) {
    return (int)(__brev((unsigned)x) >> 19);
}

// ---------------- twiddle table ----------------
__global__ void k_twiddle() {
    int j = blockIdx.x * blockDim.x + threadIdx.x;
    if (j < 2048) {
        double a = -2.0 * 3.14159265358979323846 * (double)j / (double)NFFT;
        g_tw2[j] = make_float2((float)cos(a), (float)sin(a));
    }
}

// ---------------- fp32 -> fp16 hi/lo split ----------------
__global__ void k_split2(const float* __restrict__ in, __half* __restrict__ hi,
                         __half* __restrict__ lo, int n4)
{
    int i = blockIdx.x * blockDim.x + threadIdx.x;
    if (i >= n4) return;
    float4 v = ((const float4*)in)[i];
    __half h0 = __float2half(v.x), h1 = __float2half(v.y);
    __half h2 = __float2half(v.z), h3 = __float2half(v.w);
    __half2 hh0 = {h0, h1}, hh1 = {h2, h3};
    ((__half2*)hi)[i * 2 + 0] = hh0;
    ((__half2*)hi)[i * 2 + 1] = hh1;
    __half2 ll0 = {__float2half(v.x - __half2float(h0)), __float2half(v.y - __half2float(h1))};
    __half2 ll1 = {__float2half(v.z - __half2float(h2)), __float2half(v.w - __half2float(h3))};
    ((__half2*)lo)[i * 2 + 0] = ll0;
    ((__half2*)lo)[i * 2 + 1] = ll1;
}

// ---------------- fp32 -> fp16 single ----------------
__global__ void k_split1(const float* __restrict__ in, __half* __restrict__ hi, int n4)
{
    int i = blockIdx.x * blockDim.x + threadIdx.x;
    if (i >= n4) return;
    float4 v = ((const float4*)in)[i];
    __half2 hh0 = {__float2half(v.x), __float2half(v.y)};
    __half2 hh1 = {__float2half(v.z), __float2half(v.w)};
    ((__half2*)hi)[i * 2 + 0] = hh0;
    ((__half2*)hi)[i * 2 + 1] = hh1;
}

// ================= GEMM 1: in_proj, CTA 128x256, warp 64x64, 4-stage =================
__global__ __launch_bounds__(256, 1)
void k_gemm_in(const __half* __restrict__ Ah, const __half* __restrict__ Al,
               const __half* __restrict__ Bw, const float* __restrict__ bias)
{
    extern __shared__ __align__(128) unsigned char dsm[];
    const uint32_t sb = smem_u32(dsm);
    const int tid  = threadIdx.x;
    const int lane = tid & 31;
    const int wid  = tid >> 5;
    const int wm   = wid >> 2;         // 0..1
    const int wn   = wid & 3;          // 0..3
    const int m0 = blockIdx.y * 128;
    const int n0 = blockIdx.x * 256;

    const int rw = tid >> 2, cw = tid & 3;
    const uint32_t so0 = swz((uint32_t)(rw * 64 + cw * 16));
    const __half* pAh = Ah + (size_t)(m0 + rw) * KDIM + cw * 8;
    const __half* pAl = Al + (size_t)(m0 + rw) * KDIM + cw * 8;
    const __half* pB  = Bw + (size_t)(n0 + rw) * KDIM + cw * 8;
    const size_t RB = (size_t)64 * KDIM;   // +64 rows

#define LOADST(st, k0) do {                                                   \
        uint32_t base = sb + (uint32_t)(st) * STAGE_BYTES;                    \
        cpa16(base + so0,                 pAh + (k0));                        \
        cpa16(base + so0 + 4096,          pAh + (k0) + RB);                   \
        cpa16(base + OFF_AL + so0,        pAl + (k0));                        \
        cpa16(base + OFF_AL + so0 + 4096, pAl + (k0) + RB);                   \
        cpa16(base + OFF_B + so0,         pB + (k0));                         \
        cpa16(base + OFF_B + so0 + 4096,  pB + (k0) + RB);                    \
        cpa16(base + OFF_B + so0 + 8192,  pB + (k0) + 2 * RB);                \
        cpa16(base + OFF_B + so0 + 12288, pB + (k0) + 3 * RB);                \
        CPA_COMMIT();                                                         \
    } while (0)

    uint32_t aoff[4], boff[8];
    {
        int ra = lane & 15, ka = (lane >> 4) * 16;
        int rb = lane & 7,  kb = ((lane >> 3) & 1) * 16;
#pragma unroll
        for (int mi = 0; mi < 4; mi++)
            aoff[mi] = swz((uint32_t)((wm * 64 + mi * 16 + ra) * 64 + ka));
#pragma unroll
        for (int ni = 0; ni < 8; ni++)
            boff[ni] = swz((uint32_t)((wn * 64 + ni * 8 + rb) * 64 + kb));
    }

    float acc[4][8][4];
#pragma unroll
    for (int mi = 0; mi < 4; mi++)
#pragma unroll
        for (int ni = 0; ni < 8; ni++)
#pragma unroll
            for (int r = 0; r < 4; r++) acc[mi][ni][r] = 0.f;

    LOADST(0, 0);
    LOADST(1, 1 * Bb_K);
    LOADST(2, 2 * Bb_K);

    for (int i = 0; i < NCHUNK; i++) {
        if (i + 2 < NCHUNK)      { CPA_WAIT2(); }
        else if (i + 1 < NCHUNK) { CPA_WAIT1(); }
        else                     { CPA_WAIT0(); }
        __syncthreads();
        if (i + 3 < NCHUNK) LOADST((i + 3) & 3, (i + 3) * Bb_K);

        uint32_t base = sb + (uint32_t)(i & 3) * STAGE_BYTES;
#pragma unroll
        for (int s = 0; s < 2; s++) {
            // pre-swz offsets have bit5 clear -> swz(off + s*32) == swz(off) ^ (s*32)
            const uint32_t sx = (uint32_t)(s * 32);
            uint32_t ah[4][4], al[4][4], b[8][2];
#pragma unroll
            for (int mi = 0; mi < 4; mi++) {
                LDX4(ah[mi], base + (aoff[mi] ^ sx));
                LDX4(al[mi], base + OFF_AL + (aoff[mi] ^ sx));
            }
#pragma unroll
            for (int ni = 0; ni < 8; ni++)
                LDX2(b[ni], base + OFF_B + (boff[ni] ^ sx));
#pragma unroll
            for (int mi = 0; mi < 4; mi++)
#pragma unroll
                for (int ni = 0; ni < 8; ni++) {
                    MMA16816H(acc[mi][ni], ah[mi], b[ni][0], b[ni][1]);
                    MMA16816H(acc[mi][ni], al[mi], b[ni][0], b[ni][1]);
                }
        }
    }
#undef LOADST
    __syncthreads();

    // epilogue: transpose via smem [256 n][132], store (b,c,l)
    float* ep = (float*)dsm;
    const int r  = lane >> 2;
    const int cc = 2 * (lane & 3);
#pragma unroll
    for (int mi = 0; mi < 4; mi++)
#pragma unroll
        for (int ni = 0; ni < 8; ni++) {
            int mloc = wm * 64 + mi * 16 + r;
            int nloc = wn * 64 + ni * 8 + cc;
            const float* a = acc[mi][ni];
            ep[nloc * 132 + mloc]           = a[0];
            ep[(nloc + 1) * 132 + mloc]     = a[1];
            ep[nloc * 132 + mloc + 8]       = a[2];
            ep[(nloc + 1) * 132 + mloc + 8] = a[3];
        }
    __syncthreads();

    const float* src = ep + tid * 132;
    const int b  = m0 >> 12;
    const int l0 = m0 & (LL - 1);
    const float bi = bias[n0 + tid];
    float* dst = g_u + ((size_t)b * N3 + n0 + tid) * LL + l0;
#pragma unroll
    for (int j = 0; j < 32; j++) {
        float4 v = *(const float4*)(src + j * 4);
        v.x += bi; v.y += bi; v.z += bi; v.w += bi;
        *(float4*)(dst + j * 4) = v;
    }
}

// ================= GEMM 2: out_proj, CTA 128x256, warp 64x64, A trans, 4-stage =================
__global__ __launch_bounds__(256, 1)
void k_gemm_out(const __half* __restrict__ Ah, const __half* __restrict__ Al,
                const __half* __restrict__ Bw,
                const float* __restrict__ bias, float* __restrict__ Out)
{
    extern __shared__ __align__(128) unsigned char dsm[];
    const uint32_t sb = smem_u32(dsm);
    const int tid  = threadIdx.x;
    const int lane = tid & 31;
    const int wid  = tid >> 5;
    const int wm   = wid >> 2;
    const int wn   = wid & 3;
    const int m0 = blockIdx.y * 128;
    const int n0 = blockIdx.x * 256;
    const int bb = m0 >> 12;
    const int l0 = m0 & (LL - 1);

    // A (trans): tile [32 k][128 m], row = k (256B), xor swizzle
    const int rA = tid >> 4, cA = tid & 15;
    const uint32_t soA = (uint32_t)(rA * 256 + ((cA ^ (rA & 7)) << 4));
    const __half* pAh = Ah + ((size_t)bb * DD + rA) * LL + l0 + cA * 8;
    const __half* pAl = Al + ((size_t)bb * DD + rA) * LL + l0 + cA * 8;
    const size_t RA = (size_t)16 * LL;

    // B: 256 rows x 64 B
    const int rw = tid >> 2, cw = tid & 3;
    const uint32_t so0 = swz((uint32_t)(rw * 64 + cw * 16));
    const __half* pB = Bw + (size_t)(n0 + rw) * KDIM + cw * 8;
    const size_t RB = (size_t)64 * KDIM;

#define LOADST2(st, ci) do {                                                  \
        uint32_t base = sb + (uint32_t)(st) * STAGE_BYTES;                    \
        size_t ko = (size_t)(ci) * Bb_K * LL;                                 \
        int kb = (ci) * Bb_K;                                                 \
        cpa16(base + soA,                 pAh + ko);                          \
        cpa16(base + soA + 4096,          pAh + ko + RA);                     \
        cpa16(base + OFF_AL + soA,        pAl + ko);                          \
        cpa16(base + OFF_AL + soA + 4096, pAl + ko + RA);                     \
        cpa16(base + OFF_B + so0,         pB + kb);                           \
        cpa16(base + OFF_B + so0 + 4096,  pB + kb + RB);                      \
        cpa16(base + OFF_B + so0 + 8192,  pB + kb + 2 * RB);                  \
        cpa16(base + OFF_B + so0 + 12288, pB + kb + 3 * RB);                  \
        CPA_COMMIT();                                                         \
    } while (0)

    uint32_t aoffT[4][2], boff[8];
    {
        int kr = (lane & 7) + ((lane >> 4) << 3);
        int msub = ((lane >> 3) & 1) * 8;
        int rb = lane & 7, kb = ((lane >> 3) & 1) * 16;
#pragma unroll
        for (int mi = 0; mi < 4; mi++)
#pragma unroll
            for (int s = 0; s < 2; s++) {
                int row = s * 16 + kr;
                int mcChunk = (wm * 64 + mi * 16 + msub) >> 3;
                aoffT[mi][s] = (uint32_t)(row * 256 + ((mcChunk ^ (row & 7)) << 4));
            }
#pragma unroll
        for (int ni = 0; ni < 8; ni++)
            boff[ni] = swz((uint32_t)((wn * 64 + ni * 8 + rb) * 64 + kb));
    }

    float acc[4][8][4];
#pragma unroll
    for (int mi = 0; mi < 4; mi++)
#pragma unroll
        for (int ni = 0; ni < 8; ni++)
#pragma unroll
            for (int r = 0; r < 4; r++) acc[mi][ni][r] = 0.f;

    LOADST2(0, 0);
    LOADST2(1, 1);
    LOADST2(2, 2);

    for (int i = 0; i < NCHUNK; i++) {
        if (i + 2 < NCHUNK)      { CPA_WAIT2(); }
        else if (i + 1 < NCHUNK) { CPA_WAIT1(); }
        else                     { CPA_WAIT0(); }
        __syncthreads();
        if (i + 3 < NCHUNK) LOADST2((i + 3) & 3, i + 3);

        uint32_t base = sb + (uint32_t)(i & 3) * STAGE_BYTES;
#pragma unroll
        for (int s = 0; s < 2; s++) {
            const uint32_t sx = (uint32_t)(s * 32);
            uint32_t ah[4][4], al[4][4], b[8][2];
#pragma unroll
            for (int mi = 0; mi < 4; mi++) {
                LDX4T(ah[mi], base + aoffT[mi][s]);
                LDX4T(al[mi], base + OFF_AL + aoffT[mi][s]);
            }
#pragma unroll
            for (int ni = 0; ni < 8; ni++)
                LDX2(b[ni], base + OFF_B + (boff[ni] ^ sx));
#pragma unroll
            for (int mi = 0; mi < 4; mi++)
#pragma unroll
                for (int ni = 0; ni < 8; ni++) {
                    MMA16816H(acc[mi][ni], ah[mi], b[ni][0], b[ni][1]);
                    MMA16816H(acc[mi][ni], al[mi], b[ni][0], b[ni][1]);
                }
        }
    }
#undef LOADST2
    __syncthreads();

    // epilogue: smem [128 m][260], row-major store
    float* ep = (float*)dsm;
    const int r  = lane >> 2;
    const int cc = 2 * (lane & 3);
#pragma unroll
    for (int mi = 0; mi < 4; mi++)
#pragma unroll
        for (int ni = 0; ni < 8; ni++) {
            int mloc = wm * 64 + mi * 16 + r;
            int nloc = wn * 64 + ni * 8 + cc;
            const float* a = acc[mi][ni];
            ep[mloc * 260 + nloc]           = a[0];
            ep[mloc * 260 + nloc + 1]       = a[1];
            ep[(mloc + 8) * 260 + nloc]     = a[2];
            ep[(mloc + 8) * 260 + nloc + 1] = a[3];
        }
    __syncthreads();

    const int erow = tid >> 1;
    const int half = tid & 1;
    const float* src = ep + erow * 260 + half * 128;
    float* dst = Out + (size_t)(m0 + erow) * 2048 + n0 + half * 128;
    const float* bp = bias + n0 + half * 128;
#pragma unroll
    for (int j = 0; j < 32; j++) {
        float4 v = *(const float4*)(src + j * 4);
        float4 bv = *(const float4*)(bp + j * 4);
        v.x += bv.x; v.y += bv.y; v.z += bv.z; v.w += bv.w;
        *(float4*)(dst + j * 4) = v;
    }
}

// ---------------- filter MLP features h(l) ----------------
__global__ __launch_bounds__(256)
void k_filter_h(const float* __restrict__ w0, const float* __restrict__ b0,
                const float* __restrict__ fr,
                const float* __restrict__ w1, const float* __restrict__ b1,
                const float* __restrict__ w2, const float* __restrict__ b2)
{
    __shared__ float hb[2][4][ORD];
    int o  = threadIdx.x & 63;
    int sl = threadIdx.x >> 6;
    int l  = blockIdx.x * 4 + sl;

    float t    = (float)l * (1.0f / (LL - 1));
    float wang = 6.28318530717958647692f * (float)l * (1.0f / LL);
    float ang  = 1e-4f * wang;
    float z0 = t, z1 = cosf(ang), z2 = -sinf(ang);
    float f = fr[o];

    float h = sinf(f * (w0[o * 3 + 0] * z0 + w0[o * 3 + 1] * z1 + w0[o * 3 + 2] * z2 + b0[o]));
    hb[0][sl][o] = h;
    __syncthreads();

    float acc = b1[o];
#pragma unroll
    for (int j = 0; j < ORD; j++) acc += w1[o * ORD + j] * hb[0][sl][j];
    h = sinf(f * acc);
    hb[1][sl][o] = h;
    __syncthreads();

    acc = b2[o];
#pragma unroll
    for (int j = 0; j < ORD; j++) acc += w2[o * ORD + j] * hb[1][sl][j];
    h = sinf(f * acc);
    g_h[(size_t)l * ORD + o] = h;
}

// ---------------- filter k(d,l) ----------------
#define MIN_DECAY (-3.0701134573253937f)
#define MAX_DECAY (-15.350567286626969f)
__global__ __launch_bounds__(256)
void k_filter_k(const float* __restrict__ W3)
{
    __shared__ float hs[64][65];
    __shared__ float ws[64][64];
    int l0 = blockIdx.x * 64;
    int d0 = blockIdx.y * 64;
    for (int i = threadIdx.x; i < 64 * 64; i += 256) {
        int r = i >> 6, cidx = i & 63;
        hs[r][cidx] = g_h[(size_t)(l0 + r) * ORD + cidx];
        ws[r][cidx] = W3[(size_t)(d0 + r) * ORD + cidx];
    }
    __syncthreads();
    for (int i = threadIdx.x; i < 64 * 64; i += 256) {
        int ll = i & 63;
        int dd = i >> 6;
        float acc = 0.f;
#pragma unroll
        for (int j = 0; j < ORD; j++) acc += ws[dd][j] * hs[ll][j];
        int d = d0 + dd, l = l0 + ll;
        float delta = MIN_DECAY + (MAX_DECAY - MIN_DECAY) * (float)d * (1.0f / (DD - 1));
        float decay = expf(-((float)l * (1.0f / (LL - 1))) * fabsf(delta));
        g_k[(size_t)d * LL + l] = acc * decay;
    }
}

// ================= FFT passes (padded split re/im, fused radix-2 pairs) =================
__device__ __forceinline__ void dif_pass(float* xr, float* xi,
                                         const float* twr, const float* twi, int sh)
{
    const int tid = threadIdx.x;
    const int Hh = 1 << sh;
    for (int t = tid; t < 2048; t += 512) {
        int j = t & (Hh - 1);
        int g = t >> sh;
        int i0 = (g << (sh + 2)) + j;
        int p0 = PD(i0), p1 = PD(i0 + Hh), p2 = PD(i0 + 2 * Hh), p3 = PD(i0 + 3 * Hh);
        float x0r = xr[p0], x0i = xi[p0], x1r = xr[p1], x1i = xi[p1];
        float x2r = xr[p2], x2i = xi[p2], x3r = xr[p3], x3i = xi[p3];
        int ti = PD(j << (11 - sh));
        float wr = twr[ti], wi = twi[ti];
        float u0r = x0r + x2r, u0i = x0i + x2i;
        float d0r = x0r - x2r, d0i = x0i - x2i;
        float u2r = d0r * wr - d0i * wi, u2i = d0r * wi + d0i * wr;
        float u1r = x1r + x3r, u1i = x1i + x3i;
        float d1r = x1r - x3r, d1i = x1i - x3i;
        float u3r = d1r * wi + d1i * wr;
        float u3i = d1i * wi - d1r * wr;
        float br = wr * wr - wi * wi, bi = 2.f * wr * wi;
        xr[p0] = u0r + u1r; xi[p0] = u0i + u1i;
        float e0r = u0r - u1r, e0i = u0i - u1i;
        xr[p1] = e0r * br - e0i * bi; xi[p1] = e0r * bi + e0i * br;
        xr[p2] = u2r + u3r; xi[p2] = u2i + u3i;
        float e1r = u2r - u3r, e1i = u2i - u3i;
        xr[p3] = e1r * br - e1i * bi; xi[p3] = e1r * bi + e1i * br;
    }
}

__device__ __forceinline__ void dit_pass(float* xr, float* xi,
                                         const float* twr, const float* twi, int sh)
{
    const int tid = threadIdx.x;
    const int h = 1 << sh;
    for (int t = tid; t < 2048; t += 512) {
        int j = t & (h - 1);
        int g = t >> sh;
        int i0 = (g << (sh + 2)) + j;
        int p0 = PD(i0), p1 = PD(i0 + h), p2 = PD(i0 + 2 * h), p3 = PD(i0 + 3 * h);
        float x0r = xr[p0], x0i = xi[p0], x1r = xr[p1], x1i = xi[p1];
        float x2r = xr[p2], x2i = xi[p2], x3r = xr[p3], x3i = xi[p3];
        int ti = PD(j << (11 - sh));
        float ar = twr[ti], ai = -twi[ti];
        float vr = ar * ar - ai * ai, vi = 2.f * ar * ai;
        float m1r = x1r * vr - x1i * vi, m1i = x1r * vi + x1i * vr;
        float t0r = x0r + m1r, t0i = x0i + m1i;
        float t1r = x0r - m1r, t1i = x0i - m1i;
        float m3r = x3r * vr - x3i * vi, m3i = x3r * vi + x3i * vr;
        float t2r = x2r + m3r, t2i = x2i + m3i;
        float t3r = x2r - m3r, t3i = x2i - m3i;
        float q2r = t2r * ar - t2i * ai, q2i = t2r * ai + t2i * ar;
        xr[p0] = t0r + q2r; xi[p0] = t0i + q2i;
        xr[p2] = t0r - q2r; xi[p2] = t0i - q2i;
        float q3r = -t3r * ai - t3i * ar;
        float q3i =  t3r * ar - t3i * ai;
        xr[p1] = t1r + q3r; xi[p1] = t1i + q3i;
        xr[p3] = t1r - q3r; xi[p3] = t1i - q3i;
    }
}

// ---------------- FFT of filter rows: 2 rows packed per block -> fp16 spectra ----------------
__global__ __launch_bounds__(512, 2) void k_fft_k()
{
    extern __shared__ float fsm[];
    float* xr  = fsm;
    float* xi  = xr + XPAD;
    float* twr = xi + XPAD;
    float* twi = twr + TPAD;
    const int d  = blockIdx.x;          // 0..1023
    const int d2 = d + DD / 2;
    const int tid = threadIdx.x;

    for (int j = tid; j < 2048; j += 512) {
        float2 w = g_tw2[j];
        int p = PD(j);
        twr[p] = w.x; twi[p] = w.y;
    }
    const float* k0 = g_k + (size_t)d  * LL;
    const float* k1 = g_k + (size_t)d2 * LL;
    for (int l = tid; l < LL; l += 512) { int p = PD(l); xr[p] = k0[l]; xi[p] = k1[l]; }
    for (int l = LL + tid; l < NFFT; l += 512) { int p = PD(l); xr[p] = 0.f; xi[p] = 0.f; }
    __syncthreads();

    for (int sh = 11; sh >= 1; sh -= 2) { dif_pass(xr, xi, twr, twi, sh); __syncthreads(); }

    for (int t = tid; t < 4096; t += 512) {
        int p0 = PD(2 * t), p1 = PD(2 * t + 1);
        float a_r = xr[p0], a_i = xi[p0], b_r = xr[p1], b_i = xi[p1];
        xr[p0] = a_r + b_r; xi[p0] = a_i + b_i;
        xr[p1] = a_r - b_r; xi[p1] = a_i - b_i;
    }
    __syncthreads();

    __half2* kfa = g_kf + (size_t)d  * NFFT;
    __half2* kfb = g_kf + (size_t)d2 * NFFT;
    for (int p = tid; p < NFFT; p += 512) {
        int j  = brev13(p);
        int q  = brev13((NFFT - j) & (NFFT - 1));
        int pp = PD(p), pq = PD(q);
        float zpr = xr[pp], zpi = xi[pp];
        float zqr = xr[pq], zqi = xi[pq];
        float ar = 0.5f * (zpr + zqr), ai = 0.5f * (zpi - zqi);
        float br = 0.5f * (zpi + zqi), bi = 0.5f * (zqr - zpr);
        kfa[p] = __floats2half2_rn(ar, ai);
        kfb[p] = __floats2half2_rn(br, bi);
    }
}

// ---------------- fused: short conv + gate + FFT conv + gate + fp16 split ----------------
__device__ __forceinline__ float sconv3(const float* __restrict__ u, int l,
                                        float wa, float wb, float wc, float bs)
{
    float acc = bs + wc * u[l];
    if (l >= 1) acc += wb * u[l - 1];
    if (l >= 2) acc += wa * u[l - 2];
    return acc;
}

__global__ __launch_bounds__(512, 2)
void k_fftconv(const float* __restrict__ sw, const float* __restrict__ sb,
               const float* __restrict__ fbias)
{
    extern __shared__ float fsm[];
    float* xr  = fsm;
    float* xi  = xr + XPAD;
    float* twr = xi + XPAD;
    float* twi = twr + TPAD;
    const int d = blockIdx.x;
    const int tid = threadIdx.x;

    for (int j = tid; j < 2048; j += 512) {
        float2 w = g_tw2[j];
        int p = PD(j);
        twr[p] = w.x; twi[p] = w.y;
    }

    const float* u01 = g_u + ((size_t)(0 * N3 + DD) + d) * LL;
    const float* u02 = g_u + ((size_t)(0 * N3 + 2 * DD) + d) * LL;
    const float* u11 = g_u + ((size_t)(1 * N3 + DD) + d) * LL;
    const float* u12 = g_u + ((size_t)(1 * N3 + 2 * DD) + d) * LL;

    {
        float w1a = sw[(DD + d) * 3 + 0], w1b = sw[(DD + d) * 3 + 1], w1c = sw[(DD + d) * 3 + 2];
        float w2a = sw[(2 * DD + d) * 3 + 0], w2b = sw[(2 * DD + d) * 3 + 1], w2c = sw[(2 * DD + d) * 3 + 2];
        float b1c = sb[DD + d], b2c = sb[2 * DD + d];
        for (int l = tid; l < LL; l += 512) {
            float v0 = sconv3(u02, l, w2a, w2b, w2c, b2c) * sconv3(u01, l, w1a, w1b, w1c, b1c);
            float v1 = sconv3(u12, l, w2a, w2b, w2c, b2c) * sconv3(u11, l, w1a, w1b, w1c, b1c);
            int p = PD(l);
            xr[p] = v0; xi[p] = v1;
        }
        for (int l = LL + tid; l < NFFT; l += 512) { int p = PD(l); xr[p] = 0.f; xi[p] = 0.f; }
    }
    __syncthreads();

    for (int sh = 11; sh >= 1; sh -= 2) { dif_pass(xr, xi, twr, twi, sh); __syncthreads(); }

    {
        const __half2* kf = g_kf + (size_t)d * NFFT;
        for (int t = tid; t < 4096; t += 512) {
            int p0 = PD(2 * t), p1 = PD(2 * t + 1);
            float a_r = xr[p0], a_i = xi[p0], b_r = xr[p1], b_i = xi[p1];
            float er = a_r + b_r, ei = a_i + b_i;
            float orr = a_r - b_r, oi = a_i - b_i;
            float2 K0 = __half22float2(kf[2 * t]);
            float2 K1 = __half22float2(kf[2 * t + 1]);
            float Er = er * K0.x - ei * K0.y,  Ei = er * K0.y + ei * K0.x;
            float Or = orr * K1.x - oi * K1.y, Oi = orr * K1.y + oi * K1.x;
            xr[p0] = Er + Or; xi[p0] = Ei + Oi;
            xr[p1] = Er - Or; xi[p1] = Ei - Oi;
        }
    }
    __syncthreads();

    for (int sh = 1; sh <= 11; sh += 2) { dit_pass(xr, xi, twr, twi, sh); __syncthreads(); }

    {
        const float* u00 = g_u + ((size_t)(0 * N3) + d) * LL;
        const float* u10 = g_u + ((size_t)(1 * N3) + d) * LL;
        float w0a = sw[d * 3 + 0], w0b = sw[d * 3 + 1], w0c = sw[d * 3 + 2];
        float w1a = sw[(DD + d) * 3 + 0], w1b = sw[(DD + d) * 3 + 1], w1c = sw[(DD + d) * 3 + 2];
        float w2a = sw[(2 * DD + d) * 3 + 0], w2b = sw[(2 * DD + d) * 3 + 1], w2c = sw[(2 * DD + d) * 3 + 2];
        float b0c = sb[d], b1c = sb[DD + d], b2c = sb[2 * DD + d];
        const float bi = fbias[d];
        const float inv = 1.0f / (float)NFFT;
        __half* gh0 = g_gh + (size_t)d * LL;
        __half* gl0 = g_gl + (size_t)d * LL;
        __half* gh1 = g_gh + ((size_t)DD + d) * LL;
        __half* gl1 = g_gl + ((size_t)DD + d) * LL;
        for (int l = tid; l < LL; l += 512) {
            int p = PD(l);
            float x0_0 = sconv3(u00, l, w0a, w0b, w0c, b0c);
            float v_0  = sconv3(u02, l, w2a, w2b, w2c, b2c) * sconv3(u01, l, w1a, w1b, w1c, b1c);
            float x0_1 = sconv3(u10, l, w0a, w0b, w0c, b0c);
            float v_1  = sconv3(u12, l, w2a, w2b, w2c, b2c) * sconv3(u11, l, w1a, w1b, w1c, b1c);
            float r0 = (xr[p] * inv + v_0 * bi) * x0_0;
            float r1 = (xi[p] * inv + v_1 * bi) * x0_1;
            __half h0 = __float2half(r0);
            __half h1 = __float2half(r1);
            gh0[l] = h0; gl0[l] = __float2half(r0 - __half2float(h0));
            gh1[l] = h1; gl1[l] = __float2half(r1 - __half2float(h1));
        }
    }
}

// ---------------- launch ----------------
extern "C" void kernel_launch(void* const* d_in, const int* in_sizes, int n_in,
                              void* d_out, int out_size)
{
    const float* x    = (const float*)d_in[0];
    const float* iw   = (const float*)d_in[1];
    const float* ib   = (const float*)d_in[2];
    const float* sw   = (const float*)d_in[3];
    const float* sb   = (const float*)d_in[4];
    const float* w0   = (const float*)d_in[5];
    const float* b0   = (const float*)d_in[6];
    const float* fr   = (const float*)d_in[7];
    const float* w1   = (const float*)d_in[8];
    const float* b1   = (const float*)d_in[9];
    const float* w2   = (const float*)d_in[10];
    const float* b2   = (const float*)d_in[11];
    const float* w3   = (const float*)d_in[12];
    const float* fb   = (const float*)d_in[13];
    const float* ow   = (const float*)d_in[14];
    const float* ob   = (const float*)d_in[15];
    float* out = (float*)d_out;

    (void)cudaFuncSetAttribute(k_fft_k,    cudaFuncAttributeMaxDynamicSharedMemorySize, FFT_SMEM);
    (void)cudaFuncSetAttribute(k_fftconv,  cudaFuncAttributeMaxDynamicSharedMemorySize, FFT_SMEM);
    (void)cudaFuncSetAttribute(k_gemm_in,  cudaFuncAttributeMaxDynamicSharedMemorySize, GEMM_SMEM);
    (void)cudaFuncSetAttribute(k_gemm_out, cudaFuncAttributeMaxDynamicSharedMemorySize, GEMM_SMEM);

    __half *xh, *xl, *wi, *gh, *gl, *wo;
    cudaGetSymbolAddress((void**)&xh, g_xh);  cudaGetSymbolAddress((void**)&xl, g_xl);
    cudaGetSymbolAddress((void**)&wi, g_wi);  cudaGetSymbolAddress((void**)&wo, g_wo);
    cudaGetSymbolAddress((void**)&gh, g_gh);  cudaGetSymbolAddress((void**)&gl, g_gl);

    int n4;
    n4 = (MROWS * KDIM) / 4;  k_split2<<<(n4 + 255) / 256, 256>>>(x,  xh, xl, n4);    // 1
    n4 = (N3 * KDIM) / 4;     k_split1<<<(n4 + 255) / 256, 256>>>(iw, wi, n4);        // 2
    n4 = (DD * KDIM) / 4;     k_split1<<<(n4 + 255) / 256, 256>>>(ow, wo, n4);        // 3
    k_gemm_in<<<dim3(N3 / 256, MROWS / 128), 256, GEMM_SMEM>>>(xh, xl, wi, ib);       // 4 (profiled)
    k_twiddle<<<4, 512>>>();                                                          // 5
    k_filter_h<<<LL / 4, 256>>>(w0, b0, fr, w1, b1, w2, b2);                          // 6
    k_filter_k<<<dim3(LL / 64, DD / 64), 256>>>(w3);                                  // 7
    k_fft_k<<<DD / 2, 512, FFT_SMEM>>>();                                             // 8
    k_fftconv<<<DD, 512, FFT_SMEM>>>(sw, sb, fb);                                     // 9
    k_gemm_out<<<dim3(2048 / 256, MROWS / 128), 256, GEMM_SMEM>>>(gh, gl, wo, ob, out); // 10
}